// round 15
// baseline (speedup 1.0000x reference)
#include <cuda_runtime.h>
#include <cuda_bf16.h>
#include <cuda_fp16.h>
#include <cstdint>

// ---------------------------------------------------------------------------
// CoAttention R14: weights pre-transposed+converted to fp16 [out][in] once
// per replay; weight GEMMs use coalesced fp16 B loads (no per-tile converts).
// Flash attention and layer structure = R13.
// ---------------------------------------------------------------------------

#define BB    8
#define NS    512
#define DM    512
#define NHEAD 8
#define DHH   64
#define DFF   2048
#define NLAY  4
#define LN_EPS 1e-5f

// ------------------------------- scratch -----------------------------------
__device__ float g_v  [BB*NS*DM];
__device__ float g_q  [BB*NS*DM];
__device__ float g_qkv[3*BB*NS*DM];
__device__ float g_sc [BB*NS*NS];
__device__ float g_ao [BB*NS*DM];
__device__ float g_tmp[BB*NS*DM];
__device__ float g_va [BB*NS*DM];
__device__ float g_qa [BB*NS*DM];
__device__ float g_vq [BB*NS*DM];
__device__ float g_qv [BB*NS*DM];
__device__ float g_ffn[BB*NS*DFF];

// fp16 transposed weights ([out][in] per matrix)
__device__ __half h_attn_w [NLAY*4*3*DM*DM];
__device__ __half h_attn_wo[NLAY*4*DM*DM];
__device__ __half h_ffn_w1 [NLAY*2*(long long)DM*DFF];
__device__ __half h_ffn_w2 [NLAY*2*(long long)DFF*DM];

// ------------------------------- helpers -----------------------------------

__device__ __forceinline__ unsigned f2h2(float a, float b) {
    __half2 h = __floats2half2_rn(a, b);
    return *reinterpret_cast<unsigned*>(&h);
}

__device__ __forceinline__ void mma16816(float* c, const unsigned* a, const unsigned* b) {
    asm volatile(
        "mma.sync.aligned.m16n8k16.row.col.f32.f16.f16.f32 "
        "{%0,%1,%2,%3}, {%4,%5,%6,%7}, {%8,%9}, {%0,%1,%2,%3};\n"
        : "+f"(c[0]), "+f"(c[1]), "+f"(c[2]), "+f"(c[3])
        : "r"(a[0]), "r"(a[1]), "r"(a[2]), "r"(a[3]), "r"(b[0]), "r"(b[1]));
}

#define LDSM4(r0, r1, r2, r3, addr) \
    asm volatile("ldmatrix.sync.aligned.m8n8.x4.shared.b16 {%0,%1,%2,%3}, [%4];" \
        : "=r"(r0), "=r"(r1), "=r"(r2), "=r"(r3) : "r"(addr))

#define SH 40
#define ROWB 80
#define A2BUF (64  * ROWB)
#define B2BUF (128 * ROWB)

#define FA_KSTRB 144
#define FA_VSTRB 272

// ------------------------------- kernels -----------------------------------

__global__ void copy_k(const float* __restrict__ src, float* __restrict__ dst, int n) {
    int i = blockIdx.x * blockDim.x + threadIdx.x;
    if (i < n) dst[i] = src[i];
}

// transpose+convert: X fp32 [R][C] -> Y fp16 [C][R]; z = matrix index.
__global__ __launch_bounds__(256) void transpose_w(
    const float* __restrict__ X, __half* __restrict__ Y, int R, int C)
{
    long long mat = blockIdx.z;
    X += mat * (long long)R * C;
    Y += mat * (long long)R * C;
    __shared__ float t[32][33];
    int c0 = blockIdx.x * 32, r0 = blockIdx.y * 32;
    int tx = threadIdx.x, ty = threadIdx.y;   // 32 x 8
    #pragma unroll
    for (int j = 0; j < 32; j += 8)
        t[ty + j][tx] = X[(long long)(r0 + ty + j) * C + c0 + tx];
    __syncthreads();
    #pragma unroll
    for (int j = 0; j < 32; j += 8)
        Y[(long long)(c0 + ty + j) * R + r0 + tx] = __float2half_rn(t[tx][ty + j]);
}

// ======== weight GEMM: A fp32 [M,K], B fp16 pre-transposed [N,K] ===========
// block 64x128, BK=32, 128 thr, warp 32x64. C = A @ B^T (+bias)(+relu).
__global__ __launch_bounds__(128) void mma_nth16(
    const float* __restrict__ A, const __half* __restrict__ Bh,
    const float* __restrict__ bias, float* __restrict__ C,
    int K, int lda, int ldb, int ldc,
    int zdiv, long long sA1, long long sA2, long long sB1, long long sB2,
    long long sC1, long long sC2, long long sBias, int relu)
{
    int z = blockIdx.z;
    int z1 = z / zdiv, z2 = z - z1 * zdiv;
    A  += z1 * sA1 + (long long)z2 * sA2;
    Bh += z1 * sB1 + (long long)z2 * sB2;
    C  += z1 * sC1 + (long long)z2 * sC2;
    if (bias) bias += (long long)z * sBias;

    __shared__ __align__(16) __half As[2][64][SH];
    __shared__ __align__(16) __half Bs[2][128][SH];

    const int tid = threadIdx.x;
    const int wid = tid >> 5, lane = tid & 31;
    const int wm = (wid >> 1) * 32, wn = (wid & 1) * 64;
    const int g = lane >> 2, t4 = lane & 3;
    const int row0 = blockIdx.y * 64, col0 = blockIdx.x * 128;

    const int a_r = tid >> 1, a_kh = (tid & 1) * 16;
    const float* Aptr = A + (long long)(row0 + a_r) * lda + a_kh;

    // B loader: 512 uint4 total; lin = i*128+tid; row = lin>>2, quad = lin&3
    const int lr = lane & 7, sel = lane >> 3;
    unsigned as0 = (unsigned)__cvta_generic_to_shared(&As[0][0][0]);
    unsigned bs0 = (unsigned)__cvta_generic_to_shared(&Bs[0][0][0]);
    unsigned aaddr = as0 + (unsigned)((wm + (sel & 1) * 8 + lr) * ROWB + (sel >> 1) * 16);
    unsigned baddr[4];
    #pragma unroll
    for (int j = 0; j < 4; j++)
        baddr[j] = bs0 + (unsigned)((wn + j * 16 + (sel >> 1) * 8 + lr) * ROWB + (sel & 1) * 16);

    float acc[2][8][4];
    #pragma unroll
    for (int mi = 0; mi < 2; mi++)
        #pragma unroll
        for (int ni = 0; ni < 8; ni++)
            #pragma unroll
            for (int r = 0; r < 4; r++) acc[mi][ni][r] = 0.f;

    {
        unsigned ah[8];
        uint4 bv[4];
        #pragma unroll
        for (int i = 0; i < 4; i++) {
            float4 v = *(const float4*)(Aptr + i * 4);
            ah[2 * i]     = f2h2(v.x, v.y);
            ah[2 * i + 1] = f2h2(v.z, v.w);
        }
        #pragma unroll
        for (int i = 0; i < 4; i++) {
            int lin = i * 128 + tid;
            int br = lin >> 2, bq = (lin & 3) * 8;
            bv[i] = *(const uint4*)(Bh + (long long)(col0 + br) * ldb + bq);
        }
        *(uint4*)(&As[0][a_r][a_kh])     = make_uint4(ah[0], ah[1], ah[2], ah[3]);
        *(uint4*)(&As[0][a_r][a_kh + 8]) = make_uint4(ah[4], ah[5], ah[6], ah[7]);
        #pragma unroll
        for (int i = 0; i < 4; i++) {
            int lin = i * 128 + tid;
            int br = lin >> 2, bq = (lin & 3) * 8;
            *(uint4*)(&Bs[0][br][bq]) = bv[i];
        }
    }
    __syncthreads();

    const int nk = K >> 5;
    for (int t = 0; t < nk; t++) {
        const int buf = t & 1;
        unsigned ah[8];
        uint4 bv[4];
        if (t + 1 < nk) {
            int k0 = (t + 1) << 5;
            #pragma unroll
            for (int i = 0; i < 4; i++) {
                float4 v = *(const float4*)(Aptr + k0 + i * 4);
                ah[2 * i]     = f2h2(v.x, v.y);
                ah[2 * i + 1] = f2h2(v.z, v.w);
            }
            #pragma unroll
            for (int i = 0; i < 4; i++) {
                int lin = i * 128 + tid;
                int br = lin >> 2, bq = (lin & 3) * 8;
                bv[i] = *(const uint4*)(Bh + (long long)(col0 + br) * ldb + k0 + bq);
            }
        }

        #pragma unroll
        for (int ks = 0; ks < 2; ks++) {
            unsigned ko = (unsigned)(ks * 32);
            unsigned ao = (unsigned)(buf * A2BUF) + ko;
            unsigned bo = (unsigned)(buf * B2BUF) + ko;
            unsigned af0[4], af1[4], bf[4][4];
            LDSM4(af0[0], af0[1], af0[2], af0[3], aaddr + ao);
            LDSM4(af1[0], af1[1], af1[2], af1[3], aaddr + 16u * ROWB + ao);
            #pragma unroll
            for (int j = 0; j < 4; j++)
                LDSM4(bf[j][0], bf[j][1], bf[j][2], bf[j][3], baddr[j] + bo);
            #pragma unroll
            for (int j = 0; j < 4; j++) {
                mma16816(acc[0][2 * j],     af0, &bf[j][0]);
                mma16816(acc[0][2 * j + 1], af0, &bf[j][2]);
                mma16816(acc[1][2 * j],     af1, &bf[j][0]);
                mma16816(acc[1][2 * j + 1], af1, &bf[j][2]);
            }
        }

        if (t + 1 < nk) {
            const int nb = (t + 1) & 1;
            *(uint4*)(&As[nb][a_r][a_kh])     = make_uint4(ah[0], ah[1], ah[2], ah[3]);
            *(uint4*)(&As[nb][a_r][a_kh + 8]) = make_uint4(ah[4], ah[5], ah[6], ah[7]);
            #pragma unroll
            for (int i = 0; i < 4; i++) {
                int lin = i * 128 + tid;
                int br = lin >> 2, bq = (lin & 3) * 8;
                *(uint4*)(&Bs[nb][br][bq]) = bv[i];
            }
            __syncthreads();
        }
    }

    #pragma unroll
    for (int mi = 0; mi < 2; mi++)
        #pragma unroll
        for (int ni = 0; ni < 8; ni++) {
            int r = row0 + wm + mi * 16 + g;
            int c = col0 + wn + ni * 8 + 2 * t4;
            float b0v = 0.f, b1v = 0.f;
            if (bias) { b0v = bias[c]; b1v = bias[c + 1]; }
            float o0 = acc[mi][ni][0] + b0v;
            float o1 = acc[mi][ni][1] + b1v;
            float o2 = acc[mi][ni][2] + b0v;
            float o3 = acc[mi][ni][3] + b1v;
            if (relu) {
                o0 = fmaxf(o0, 0.f); o1 = fmaxf(o1, 0.f);
                o2 = fmaxf(o2, 0.f); o3 = fmaxf(o3, 0.f);
            }
            *(float2*)(C + (long long)r * ldc + c)       = make_float2(o0, o1);
            *(float2*)(C + (long long)(r + 8) * ldc + c) = make_float2(o2, o3);
        }
}

// ======== NN GEMM fp32-B (final bilinear: SC @ Q), block 64x128 ============
__global__ __launch_bounds__(128) void mma_nn2h(
    const float* __restrict__ A, const float* __restrict__ B,
    const float* __restrict__ bias, float* __restrict__ C,
    int K, int lda, int ldb, int ldc,
    int zdiv, long long sA1, long long sA2, long long sB1, long long sB2,
    long long sC1, long long sC2, long long sBias, int relu)
{
    int z = blockIdx.z;
    int z1 = z / zdiv, z2 = z - z1 * zdiv;
    A += z1 * sA1 + (long long)z2 * sA2;
    B += z1 * sB1 + (long long)z2 * sB2;
    C += z1 * sC1 + (long long)z2 * sC2;
    if (bias) bias += (long long)z * sBias;

    __shared__ __align__(16) __half As[2][64][SH];
    __shared__ __align__(16) __half Bs[2][128][SH];

    const int tid = threadIdx.x;
    const int wid = tid >> 5, lane = tid & 31;
    const int wm = (wid >> 1) * 32, wn = (wid & 1) * 64;
    const int g = lane >> 2, t4 = lane & 3;
    const int row0 = blockIdx.y * 64, col0 = blockIdx.x * 128;

    const int a_r = tid >> 1, a_kh = (tid & 1) * 16;
    const float* Aptr = A + (long long)(row0 + a_r) * lda + a_kh;
    const float* Bptr = B + col0 + tid;

    const int lr = lane & 7, sel = lane >> 3;
    unsigned as0 = (unsigned)__cvta_generic_to_shared(&As[0][0][0]);
    unsigned bs0 = (unsigned)__cvta_generic_to_shared(&Bs[0][0][0]);
    unsigned aaddr = as0 + (unsigned)((wm + (sel & 1) * 8 + lr) * ROWB + (sel >> 1) * 16);
    unsigned baddr[4];
    #pragma unroll
    for (int j = 0; j < 4; j++)
        baddr[j] = bs0 + (unsigned)((wn + j * 16 + (sel >> 1) * 8 + lr) * ROWB + (sel & 1) * 16);

    float acc[2][8][4];
    #pragma unroll
    for (int mi = 0; mi < 2; mi++)
        #pragma unroll
        for (int ni = 0; ni < 8; ni++)
            #pragma unroll
            for (int r = 0; r < 4; r++) acc[mi][ni][r] = 0.f;

    {
        unsigned ah[8], bh[16];
        #pragma unroll
        for (int i = 0; i < 4; i++) {
            float4 v = *(const float4*)(Aptr + i * 4);
            ah[2 * i]     = f2h2(v.x, v.y);
            ah[2 * i + 1] = f2h2(v.z, v.w);
        }
        #pragma unroll
        for (int j = 0; j < 16; j++)
            bh[j] = f2h2(Bptr[(long long)(2 * j) * ldb], Bptr[(long long)(2 * j + 1) * ldb]);
        *(uint4*)(&As[0][a_r][a_kh])     = make_uint4(ah[0], ah[1], ah[2], ah[3]);
        *(uint4*)(&As[0][a_r][a_kh + 8]) = make_uint4(ah[4], ah[5], ah[6], ah[7]);
        *(uint4*)(&Bs[0][tid][0])  = make_uint4(bh[0],  bh[1],  bh[2],  bh[3]);
        *(uint4*)(&Bs[0][tid][8])  = make_uint4(bh[4],  bh[5],  bh[6],  bh[7]);
        *(uint4*)(&Bs[0][tid][16]) = make_uint4(bh[8],  bh[9],  bh[10], bh[11]);
        *(uint4*)(&Bs[0][tid][24]) = make_uint4(bh[12], bh[13], bh[14], bh[15]);
    }
    __syncthreads();

    const int nk = K >> 5;
    for (int t = 0; t < nk; t++) {
        const int buf = t & 1;
        unsigned ah[8], bh[16];
        if (t + 1 < nk) {
            int k0 = (t + 1) << 5;
            #pragma unroll
            for (int i = 0; i < 4; i++) {
                float4 v = *(const float4*)(Aptr + k0 + i * 4);
                ah[2 * i]     = f2h2(v.x, v.y);
                ah[2 * i + 1] = f2h2(v.z, v.w);
            }
            #pragma unroll
            for (int j = 0; j < 16; j++)
                bh[j] = f2h2(Bptr[(long long)(k0 + 2 * j) * ldb],
                             Bptr[(long long)(k0 + 2 * j + 1) * ldb]);
        }

        #pragma unroll
        for (int ks = 0; ks < 2; ks++) {
            unsigned ko = (unsigned)(ks * 32);
            unsigned ao = (unsigned)(buf * A2BUF) + ko;
            unsigned bo = (unsigned)(buf * B2BUF) + ko;
            unsigned af0[4], af1[4], bf[4][4];
            LDSM4(af0[0], af0[1], af0[2], af0[3], aaddr + ao);
            LDSM4(af1[0], af1[1], af1[2], af1[3], aaddr + 16u * ROWB + ao);
            #pragma unroll
            for (int j = 0; j < 4; j++)
                LDSM4(bf[j][0], bf[j][1], bf[j][2], bf[j][3], baddr[j] + bo);
            #pragma unroll
            for (int j = 0; j < 4; j++) {
                mma16816(acc[0][2 * j],     af0, &bf[j][0]);
                mma16816(acc[0][2 * j + 1], af0, &bf[j][2]);
                mma16816(acc[1][2 * j],     af1, &bf[j][0]);
                mma16816(acc[1][2 * j + 1], af1, &bf[j][2]);
            }
        }

        if (t + 1 < nk) {
            const int nb = (t + 1) & 1;
            *(uint4*)(&As[nb][a_r][a_kh])     = make_uint4(ah[0], ah[1], ah[2], ah[3]);
            *(uint4*)(&As[nb][a_r][a_kh + 8]) = make_uint4(ah[4], ah[5], ah[6], ah[7]);
            *(uint4*)(&Bs[nb][tid][0])  = make_uint4(bh[0],  bh[1],  bh[2],  bh[3]);
            *(uint4*)(&Bs[nb][tid][8])  = make_uint4(bh[4],  bh[5],  bh[6],  bh[7]);
            *(uint4*)(&Bs[nb][tid][16]) = make_uint4(bh[8],  bh[9],  bh[10], bh[11]);
            *(uint4*)(&Bs[nb][tid][24]) = make_uint4(bh[12], bh[13], bh[14], bh[15]);
            __syncthreads();
        }
    }

    #pragma unroll
    for (int mi = 0; mi < 2; mi++)
        #pragma unroll
        for (int ni = 0; ni < 8; ni++) {
            int r = row0 + wm + mi * 16 + g;
            int c = col0 + wn + ni * 8 + 2 * t4;
            float b0v = 0.f, b1v = 0.f;
            if (bias) { b0v = bias[c]; b1v = bias[c + 1]; }
            float o0 = acc[mi][ni][0] + b0v;
            float o1 = acc[mi][ni][1] + b1v;
            float o2 = acc[mi][ni][2] + b0v;
            float o3 = acc[mi][ni][3] + b1v;
            if (relu) {
                o0 = fmaxf(o0, 0.f); o1 = fmaxf(o1, 0.f);
                o2 = fmaxf(o2, 0.f); o3 = fmaxf(o3, 0.f);
            }
            *(float2*)(C + (long long)r * ldc + c)       = make_float2(o0, o1);
            *(float2*)(C + (long long)(r + 8) * ldc + c) = make_float2(o2, o3);
        }
}

// ======== NT GEMM fp32-B (final bilinear: PQs @ Q^T), block 64x128 =========
__global__ __launch_bounds__(128) void mma_nt2h(
    const float* __restrict__ A, const float* __restrict__ B,
    float* __restrict__ C,
    int K, int lda, int ldb, int ldc,
    int zdiv, long long sA1, long long sA2, long long sB1, long long sB2,
    long long sC1, long long sC2, float scale)
{
    int z = blockIdx.z;
    int z1 = z / zdiv, z2 = z - z1 * zdiv;
    A += z1 * sA1 + (long long)z2 * sA2;
    B += z1 * sB1 + (long long)z2 * sB2;
    C += z1 * sC1 + (long long)z2 * sC2;

    __shared__ __align__(16) __half As[2][64][SH];
    __shared__ __align__(16) __half Bs[2][128][SH];

    const int tid = threadIdx.x;
    const int wid = tid >> 5, lane = tid & 31;
    const int wm = (wid >> 1) * 32, wn = (wid & 1) * 64;
    const int g = lane >> 2, t4 = lane & 3;
    const int row0 = blockIdx.y * 64, col0 = blockIdx.x * 128;

    const int a_r = tid >> 1, a_kh = (tid & 1) * 16;
    const float* Aptr = A + (long long)(row0 + a_r) * lda + a_kh;
    const float* Bptr = B + (long long)(col0 + tid) * ldb;

    const int lr = lane & 7, sel = lane >> 3;
    unsigned as0 = (unsigned)__cvta_generic_to_shared(&As[0][0][0]);
    unsigned bs0 = (unsigned)__cvta_generic_to_shared(&Bs[0][0][0]);
    unsigned aaddr = as0 + (unsigned)((wm + (sel & 1) * 8 + lr) * ROWB + (sel >> 1) * 16);
    unsigned baddr[4];
    #pragma unroll
    for (int j = 0; j < 4; j++)
        baddr[j] = bs0 + (unsigned)((wn + j * 16 + (sel >> 1) * 8 + lr) * ROWB + (sel & 1) * 16);

    float acc[2][8][4];
    #pragma unroll
    for (int mi = 0; mi < 2; mi++)
        #pragma unroll
        for (int ni = 0; ni < 8; ni++)
            #pragma unroll
            for (int r = 0; r < 4; r++) acc[mi][ni][r] = 0.f;

    {
        unsigned ah[8], bh[16];
        #pragma unroll
        for (int i = 0; i < 4; i++) {
            float4 v = *(const float4*)(Aptr + i * 4);
            ah[2 * i]     = f2h2(v.x, v.y);
            ah[2 * i + 1] = f2h2(v.z, v.w);
        }
        #pragma unroll
        for (int i = 0; i < 8; i++) {
            float4 v = *(const float4*)(Bptr + i * 4);
            bh[2 * i]     = f2h2(v.x, v.y);
            bh[2 * i + 1] = f2h2(v.z, v.w);
        }
        *(uint4*)(&As[0][a_r][a_kh])     = make_uint4(ah[0], ah[1], ah[2], ah[3]);
        *(uint4*)(&As[0][a_r][a_kh + 8]) = make_uint4(ah[4], ah[5], ah[6], ah[7]);
        *(uint4*)(&Bs[0][tid][0])  = make_uint4(bh[0],  bh[1],  bh[2],  bh[3]);
        *(uint4*)(&Bs[0][tid][8])  = make_uint4(bh[4],  bh[5],  bh[6],  bh[7]);
        *(uint4*)(&Bs[0][tid][16]) = make_uint4(bh[8],  bh[9],  bh[10], bh[11]);
        *(uint4*)(&Bs[0][tid][24]) = make_uint4(bh[12], bh[13], bh[14], bh[15]);
    }
    __syncthreads();

    const int nk = K >> 5;
    for (int t = 0; t < nk; t++) {
        const int buf = t & 1;
        unsigned ah[8], bh[16];
        if (t + 1 < nk) {
            int k0 = (t + 1) << 5;
            #pragma unroll
            for (int i = 0; i < 4; i++) {
                float4 v = *(const float4*)(Aptr + k0 + i * 4);
                ah[2 * i]     = f2h2(v.x, v.y);
                ah[2 * i + 1] = f2h2(v.z, v.w);
            }
            #pragma unroll
            for (int i = 0; i < 8; i++) {
                float4 v = *(const float4*)(Bptr + k0 + i * 4);
                bh[2 * i]     = f2h2(v.x, v.y);
                bh[2 * i + 1] = f2h2(v.z, v.w);
            }
        }

        #pragma unroll
        for (int ks = 0; ks < 2; ks++) {
            unsigned ko = (unsigned)(ks * 32);
            unsigned ao = (unsigned)(buf * A2BUF) + ko;
            unsigned bo = (unsigned)(buf * B2BUF) + ko;
            unsigned af0[4], af1[4], bf[4][4];
            LDSM4(af0[0], af0[1], af0[2], af0[3], aaddr + ao);
            LDSM4(af1[0], af1[1], af1[2], af1[3], aaddr + 16u * ROWB + ao);
            #pragma unroll
            for (int j = 0; j < 4; j++)
                LDSM4(bf[j][0], bf[j][1], bf[j][2], bf[j][3], baddr[j] + bo);
            #pragma unroll
            for (int j = 0; j < 4; j++) {
                mma16816(acc[0][2 * j],     af0, &bf[j][0]);
                mma16816(acc[0][2 * j + 1], af0, &bf[j][2]);
                mma16816(acc[1][2 * j],     af1, &bf[j][0]);
                mma16816(acc[1][2 * j + 1], af1, &bf[j][2]);
            }
        }

        if (t + 1 < nk) {
            const int nb = (t + 1) & 1;
            *(uint4*)(&As[nb][a_r][a_kh])     = make_uint4(ah[0], ah[1], ah[2], ah[3]);
            *(uint4*)(&As[nb][a_r][a_kh + 8]) = make_uint4(ah[4], ah[5], ah[6], ah[7]);
            *(uint4*)(&Bs[nb][tid][0])  = make_uint4(bh[0],  bh[1],  bh[2],  bh[3]);
            *(uint4*)(&Bs[nb][tid][8])  = make_uint4(bh[4],  bh[5],  bh[6],  bh[7]);
            *(uint4*)(&Bs[nb][tid][16]) = make_uint4(bh[8],  bh[9],  bh[10], bh[11]);
            *(uint4*)(&Bs[nb][tid][24]) = make_uint4(bh[12], bh[13], bh[14], bh[15]);
            __syncthreads();
        }
    }

    #pragma unroll
    for (int mi = 0; mi < 2; mi++)
        #pragma unroll
        for (int ni = 0; ni < 8; ni++) {
            int r = row0 + wm + mi * 16 + g;
            int c = col0 + wn + ni * 8 + 2 * t4;
            *(float2*)(C + (long long)r * ldc + c) =
                make_float2(acc[mi][ni][0] * scale, acc[mi][ni][1] * scale);
            *(float2*)(C + (long long)(r + 8) * ldc + c) =
                make_float2(acc[mi][ni][2] * scale, acc[mi][ni][3] * scale);
        }
}

// ======== fused flash attention (R13 version) ==============================
__global__ __launch_bounds__(128) void flash_attn(
    const float* __restrict__ Qg, const float* __restrict__ Kg,
    const float* __restrict__ Vg, const int* __restrict__ mask,
    float* __restrict__ Og)
{
    __shared__ __align__(16) __half Qs[64 * (FA_KSTRB / 2)];
    __shared__ __align__(16) __half Ks[128 * (FA_KSTRB / 2)];
    __shared__ __align__(16) __half Vs[64 * (FA_VSTRB / 2)];
    __shared__ float msk[NS];

    const int bh = blockIdx.y;
    const int b = bh >> 3, h = bh & 7;
    const int q0 = blockIdx.x * 64;
    const float* Qp = Qg + (long long)b * NS * DM + h * DHH;
    const float* Kp = Kg + (long long)b * NS * DM + h * DHH;
    const float* Vp = Vg + (long long)b * NS * DM + h * DHH;

    const int tid = threadIdx.x;
    const int wid = tid >> 5, lane = tid & 31;
    const int g = lane >> 2, t4 = lane & 3;
    const int lr = lane & 7, sel = lane >> 3;

    unsigned qs_b = (unsigned)__cvta_generic_to_shared(Qs);
    unsigned ks_b = (unsigned)__cvta_generic_to_shared(Ks);
    unsigned vs_b = (unsigned)__cvta_generic_to_shared(Vs);

    for (int j = tid; j < NS; j += 128)
        msk[j] = mask[b * NS + j] ? 0.f : -1e9f;

    {
        int r = tid >> 1, kh = (tid & 1) * 32;
        const float* qp = Qp + (long long)(q0 + r) * DM + kh;
        __half* dst = Qs + r * (FA_KSTRB / 2) + kh;
        #pragma unroll
        for (int i = 0; i < 8; i++) {
            float4 v = *(const float4*)(qp + i * 4);
            *(uint2*)(dst + i * 4) = make_uint2(f2h2(v.x, v.y), f2h2(v.z, v.w));
        }
    }

    unsigned qa = qs_b + (unsigned)((wid * 16 + (sel & 1) * 8 + lr) * FA_KSTRB + (sel >> 1) * 16);

    float m0 = -1e30f, m1 = -1e30f, l0 = 0.f, l1 = 0.f;
    float o[8][4];
    #pragma unroll
    for (int p = 0; p < 8; p++)
        #pragma unroll
        for (int r = 0; r < 4; r++) o[p][r] = 0.f;

    for (int c = 0; c < 4; c++) {
        const int j0 = c * 128;
        {
            const float* kp = Kp + (long long)(j0 + tid) * DM;
            __half* dst = Ks + tid * (FA_KSTRB / 2);
            #pragma unroll
            for (int i = 0; i < 16; i++) {
                float4 v = *(const float4*)(kp + i * 4);
                *(uint2*)(dst + i * 4) = make_uint2(f2h2(v.x, v.y), f2h2(v.z, v.w));
            }
            const float* vp = Vp + (long long)(j0 + tid) * DM;
            __half* base = Vs + tid;
            #pragma unroll
            for (int i = 0; i < 16; i++) {
                float4 v = *(const float4*)(vp + i * 4);
                base[(4 * i + 0) * (FA_VSTRB / 2)] = __float2half_rn(v.x);
                base[(4 * i + 1) * (FA_VSTRB / 2)] = __float2half_rn(v.y);
                base[(4 * i + 2) * (FA_VSTRB / 2)] = __float2half_rn(v.z);
                base[(4 * i + 3) * (FA_VSTRB / 2)] = __float2half_rn(v.w);
            }
        }
        __syncthreads();

        float s[16][4];
        #pragma unroll
        for (int p = 0; p < 16; p++)
            #pragma unroll
            for (int r = 0; r < 4; r++) s[p][r] = 0.f;

        #pragma unroll
        for (int ks = 0; ks < 4; ks++) {
            unsigned af[4];
            LDSM4(af[0], af[1], af[2], af[3], qa + ks * 32);
            #pragma unroll
            for (int p = 0; p < 8; p++) {
                unsigned bf[4];
                unsigned ba = ks_b + (unsigned)((p * 16 + (sel >> 1) * 8 + lr) * FA_KSTRB
                                                + (sel & 1) * 16) + ks * 32;
                LDSM4(bf[0], bf[1], bf[2], bf[3], ba);
                mma16816(s[2 * p],     af, &bf[0]);
                mma16816(s[2 * p + 1], af, &bf[2]);
            }
        }

        float cm0 = -1e30f, cm1 = -1e30f;
        #pragma unroll
        for (int p = 0; p < 16; p++) {
            int col = j0 + p * 8 + 2 * t4;
            float mv0 = msk[col], mv1 = msk[col + 1];
            s[p][0] = s[p][0] * 0.125f + mv0;
            s[p][1] = s[p][1] * 0.125f + mv1;
            s[p][2] = s[p][2] * 0.125f + mv0;
            s[p][3] = s[p][3] * 0.125f + mv1;
            cm0 = fmaxf(cm0, fmaxf(s[p][0], s[p][1]));
            cm1 = fmaxf(cm1, fmaxf(s[p][2], s[p][3]));
        }
        cm0 = fmaxf(cm0, __shfl_xor_sync(0xffffffffu, cm0, 1));
        cm0 = fmaxf(cm0, __shfl_xor_sync(0xffffffffu, cm0, 2));
        cm1 = fmaxf(cm1, __shfl_xor_sync(0xffffffffu, cm1, 1));
        cm1 = fmaxf(cm1, __shfl_xor_sync(0xffffffffu, cm1, 2));

        float nm0 = fmaxf(m0, cm0), nm1 = fmaxf(m1, cm1);
        float sc0 = __expf(m0 - nm0), sc1 = __expf(m1 - nm1);
        m0 = nm0; m1 = nm1;
        l0 *= sc0; l1 *= sc1;
        #pragma unroll
        for (int p = 0; p < 8; p++) {
            o[p][0] *= sc0; o[p][1] *= sc0;
            o[p][2] *= sc1; o[p][3] *= sc1;
        }

        #pragma unroll
        for (int p = 0; p < 16; p++) {
            s[p][0] = __expf(s[p][0] - m0);
            s[p][1] = __expf(s[p][1] - m0);
            s[p][2] = __expf(s[p][2] - m1);
            s[p][3] = __expf(s[p][3] - m1);
            l0 += s[p][0] + s[p][1];
            l1 += s[p][2] + s[p][3];
        }

        #pragma unroll
        for (int p = 0; p < 8; p++) {
            unsigned af[4];
            af[0] = f2h2(s[2 * p][0],     s[2 * p][1]);
            af[1] = f2h2(s[2 * p][2],     s[2 * p][3]);
            af[2] = f2h2(s[2 * p + 1][0], s[2 * p + 1][1]);
            af[3] = f2h2(s[2 * p + 1][2], s[2 * p + 1][3]);
            #pragma unroll
            for (int n = 0; n < 4; n++) {
                unsigned bf[4];
                unsigned ba = vs_b + (unsigned)((n * 16 + (sel >> 1) * 8 + lr) * FA_VSTRB
                                                + ((sel & 1) * 8 + p * 16) * 2);
                LDSM4(bf[0], bf[1], bf[2], bf[3], ba);
                mma16816(o[2 * n],     af, &bf[0]);
                mma16816(o[2 * n + 1], af, &bf[2]);
            }
        }
        __syncthreads();
    }

    l0 += __shfl_xor_sync(0xffffffffu, l0, 1);
    l0 += __shfl_xor_sync(0xffffffffu, l0, 2);
    l1 += __shfl_xor_sync(0xffffffffu, l1, 1);
    l1 += __shfl_xor_sync(0xffffffffu, l1, 2);
    const float inv0 = 1.f / l0, inv1 = 1.f / l1;

    {
        int r0 = q0 + wid * 16 + g;
        float* out0 = Og + ((long long)b * NS + r0) * DM + h * DHH;
        float* out1 = out0 + 8ll * DM;
        #pragma unroll
        for (int p = 0; p < 8; p++) {
            int cc = p * 8 + 2 * t4;
            *(float2*)(out0 + cc) = make_float2(o[p][0] * inv0, o[p][1] * inv0);
            *(float2*)(out1 + cc) = make_float2(o[p][2] * inv1, o[p][3] * inv1);
        }
    }
}

// out[row] = LN(x[row] + y[row]) * g + b.
__global__ __launch_bounds__(256) void ln_add(
    const float* __restrict__ X, const float* __restrict__ Y,
    const float* __restrict__ g, const float* __restrict__ be,
    float* __restrict__ O)
{
    int row = blockIdx.x;
    const float* xp = X + (long long)row * DM;
    const float* yp = Y + (long long)row * DM;
    float* op = O + (long long)row * DM;
    int tid = threadIdx.x;

    float a0 = xp[tid] + yp[tid];
    float a1 = xp[tid + 256] + yp[tid + 256];

    __shared__ float r1[256];
    __shared__ float r2[256];
    r1[tid] = a0 + a1;
    r2[tid] = a0 * a0 + a1 * a1;
    __syncthreads();
    for (int s = 128; s > 0; s >>= 1) {
        if (tid < s) { r1[tid] += r1[tid + s]; r2[tid] += r2[tid + s]; }
        __syncthreads();
    }
    float mean = r1[0] * (1.f / DM);
    float var  = r2[0] * (1.f / DM) - mean * mean;
    float rstd = rsqrtf(var + LN_EPS);
    op[tid]       = (a0 - mean) * rstd * g[tid]       + be[tid];
    op[tid + 256] = (a1 - mean) * rstd * g[tid + 256] + be[tid + 256];
}

__global__ void vmul_k(const float* __restrict__ v, const float* __restrict__ w,
                       float* __restrict__ o, int n) {
    int i = blockIdx.x * blockDim.x + threadIdx.x;
    if (i < n) o[i] = v[i] * w[i & (DM - 1)];
}

__global__ __launch_bounds__(256) void softmax_final(
    float* __restrict__ S, const int* __restrict__ vmask,
    const int* __restrict__ qmask, const float* __restrict__ attb)
{
    int row = blockIdx.x;
    int b = row >> 9, i = row & (NS - 1);
    int rowpad = (vmask[b * NS + i] == 0);
    float ab = attb[0];
    float* Sp = S + (long long)row * NS;
    int tid = threadIdx.x;

    float v0 = (rowpad || qmask[b * NS + tid] == 0)       ? -1e9f : Sp[tid] + ab;
    float v1 = (rowpad || qmask[b * NS + tid + 256] == 0) ? -1e9f : Sp[tid + 256] + ab;

    __shared__ float red[256];
    red[tid] = fmaxf(v0, v1);
    __syncthreads();
    for (int s = 128; s > 0; s >>= 1) {
        if (tid < s) red[tid] = fmaxf(red[tid], red[tid + s]);
        __syncthreads();
    }
    float m = red[0];
    __syncthreads();

    float e0 = __expf(v0 - m), e1 = __expf(v1 - m);
    red[tid] = e0 + e1;
    __syncthreads();
    for (int s = 128; s > 0; s >>= 1) {
        if (tid < s) red[tid] += red[tid + s];
        __syncthreads();
    }
    float inv = 1.f / red[0];
    Sp[tid]       = e0 * inv;
    Sp[tid + 256] = e1 * inv;
}

__global__ void final_out_k(const float* __restrict__ V, const float* __restrict__ T,
                            float* __restrict__ out) {
    int b = blockIdx.x;
    int k = threadIdx.x;
    const float* vp = V + (long long)b * NS * DM;
    const float* tp = T + (long long)b * NS * DM;
    float acc = 0.f;
    #pragma unroll 4
    for (int i = 0; i < NS; i++)
        acc = fmaf(vp[(long long)i * DM + k], tp[(long long)i * DM + k], acc);
    out[b * DM + k] = acc * (1.f / 512.f);
}

// ------------------------------- host side ---------------------------------

static void run_mha(const float* xq, const float* xkv, const int* mask,
                    const __half* wT, const float* b,
                    const __half* woT, const float* bo,
                    float* QKV, float* AO, float* out)
{
    const long long NT = (long long)BB * NS * DM;
    const long long WSTRIDE = (long long)DM * DM;
    const dim3 gP(DM / 128, (BB * NS) / 64, 1);

    if (xq == xkv) {
        mma_nth16<<<dim3(DM / 128, (BB * NS) / 64, 3), 128>>>(
            xq, wT, b, QKV, DM, DM, DM, DM,
            3, 0, 0, 0, WSTRIDE, 0, NT, DM, 0);
    } else {
        mma_nth16<<<gP, 128>>>(
            xq, wT, b, QKV, DM, DM, DM, DM,
            1, 0, 0, 0, 0, 0, 0, DM, 0);
        mma_nth16<<<dim3(DM / 128, (BB * NS) / 64, 2), 128>>>(
            xkv, wT + WSTRIDE, b + DM, QKV + NT, DM, DM, DM, DM,
            2, 0, 0, 0, WSTRIDE, 0, NT, DM, 0);
    }

    flash_attn<<<dim3(NS / 64, BB * NHEAD), 128>>>(
        QKV, QKV + NT, QKV + 2 * NT, mask, AO);

    mma_nth16<<<gP, 128>>>(
        AO, woT, bo, out, DM, DM, DM, DM,
        1, 0, 0, 0, 0, 0, 0, DM, 0);
}

extern "C" void kernel_launch(void* const* d_in, const int* in_sizes, int n_in,
                              void* d_out, int out_size)
{
    const float *v_in, *q_in, *attn_w, *attn_b, *attn_wo, *attn_bo;
    const float *ln_g, *ln_b, *fw1, *fb1, *fw2, *fb2, *att_w, *att_b;
    const int *v_mask, *q_mask;

    if (in_sizes[2] == BB * NS) {   // dict order
        v_in    = (const float*)d_in[0];
        q_in    = (const float*)d_in[1];
        v_mask  = (const int*)  d_in[2];
        q_mask  = (const int*)  d_in[3];
        attn_w  = (const float*)d_in[4];
        attn_b  = (const float*)d_in[5];
        attn_wo = (const float*)d_in[6];
        attn_bo = (const float*)d_in[7];
        ln_g    = (const float*)d_in[8];
        ln_b    = (const float*)d_in[9];
        fw1     = (const float*)d_in[10];
        fb1     = (const float*)d_in[11];
        fw2     = (const float*)d_in[12];
        fb2     = (const float*)d_in[13];
        att_w   = (const float*)d_in[14];
        att_b   = (const float*)d_in[15];
    } else {                        // signature order
        v_in    = (const float*)d_in[0];
        q_in    = (const float*)d_in[1];
        attn_w  = (const float*)d_in[2];
        attn_b  = (const float*)d_in[3];
        attn_wo = (const float*)d_in[4];
        attn_bo = (const float*)d_in[5];
        ln_g    = (const float*)d_in[6];
        ln_b    = (const float*)d_in[7];
        fw1     = (const float*)d_in[8];
        fb1     = (const float*)d_in[9];
        fw2     = (const float*)d_in[10];
        fb2     = (const float*)d_in[11];
        att_w   = (const float*)d_in[12];
        att_b   = (const float*)d_in[13];
        v_mask  = (const int*)  d_in[14];
        q_mask  = (const int*)  d_in[15];
    }

    float *V, *Q, *QKV, *SC, *AO, *TMP, *VA, *QA, *VQ, *QV, *FFN;
    __half *HW, *HWO, *HF1, *HF2;
    cudaGetSymbolAddress((void**)&V,   g_v);
    cudaGetSymbolAddress((void**)&Q,   g_q);
    cudaGetSymbolAddress((void**)&QKV, g_qkv);
    cudaGetSymbolAddress((void**)&SC,  g_sc);
    cudaGetSymbolAddress((void**)&AO,  g_ao);
    cudaGetSymbolAddress((void**)&TMP, g_tmp);
    cudaGetSymbolAddress((void**)&VA,  g_va);
    cudaGetSymbolAddress((void**)&QA,  g_qa);
    cudaGetSymbolAddress((void**)&VQ,  g_vq);
    cudaGetSymbolAddress((void**)&QV,  g_qv);
    cudaGetSymbolAddress((void**)&FFN, g_ffn);
    cudaGetSymbolAddress((void**)&HW,  h_attn_w);
    cudaGetSymbolAddress((void**)&HWO, h_attn_wo);
    cudaGetSymbolAddress((void**)&HF1, h_ffn_w1);
    cudaGetSymbolAddress((void**)&HF2, h_ffn_w2);

    const int NTOK = BB * NS * DM;
    const long long NT = (long long)NTOK;
    const long long SBATCH = (long long)NS * DM;

    // weight pre-transpose + fp16 conversion
    dim3 tb(32, 8, 1);
    transpose_w<<<dim3(DM / 32, DM / 32, NLAY * 4 * 3), tb>>>(attn_w,  HW,  DM, DM);
    transpose_w<<<dim3(DM / 32, DM / 32, NLAY * 4),     tb>>>(attn_wo, HWO, DM, DM);
    transpose_w<<<dim3(DFF / 32, DM / 32, NLAY * 2),    tb>>>(fw1, HF1, DM, DFF);
    transpose_w<<<dim3(DM / 32, DFF / 32, NLAY * 2),    tb>>>(fw2, HF2, DFF, DM);

    copy_k<<<(NTOK + 255) / 256, 256>>>(v_in, V, NTOK);
    copy_k<<<(NTOK + 255) / 256, 256>>>(q_in, Q, NTOK);

    const int rows = BB * NS;

    for (int i = 0; i < NLAY; i++) {
        const __half* wT  = HW  + (long long)i * 4 * 3 * DM * DM;
        const __half* woT = HWO + (long long)i * 4 * DM * DM;
        const float* ab  = attn_b  + (long long)i * 4 * 3 * DM;
        const float* abo = attn_bo + (long long)i * 4 * DM;
        const float* lg  = ln_g + (long long)i * 6 * DM;
        const float* lb  = ln_b + (long long)i * 6 * DM;

        run_mha(V, V, v_mask, wT, ab, woT, abo, QKV, AO, TMP);
        ln_add<<<rows, 256>>>(V, TMP, lg, lb, VA);

        run_mha(Q, Q, q_mask,
                wT + 3ll * DM * DM, ab + 3 * DM, woT + (long long)DM * DM, abo + DM,
                QKV, AO, TMP);
        ln_add<<<rows, 256>>>(Q, TMP, lg + DM, lb + DM, QA);

        run_mha(VA, QA, q_mask,
                wT + 6ll * DM * DM, ab + 6 * DM, woT + 2ll * DM * DM, abo + 2 * DM,
                QKV, AO, VQ);
        run_mha(QA, VQ, v_mask,
                wT + 9ll * DM * DM, ab + 9 * DM, woT + 3ll * DM * DM, abo + 3 * DM,
                QKV, AO, QV);

        ln_add<<<rows, 256>>>(V, VQ, lg + 2 * DM, lb + 2 * DM, V);
        ln_add<<<rows, 256>>>(Q, QV, lg + 3 * DM, lb + 3 * DM, Q);

        const __half* w1T = HF1 + (long long)i * 2 * DM * DFF;   // [DFF][DM]
        const __half* w2T = HF2 + (long long)i * 2 * DFF * DM;   // [DM][DFF]
        const float* b1v = fb1 + (long long)i * 2 * DFF;
        const float* b2v = fb2 + (long long)i * 2 * DM;

        mma_nth16<<<dim3(DFF / 128, rows / 64, 1), 128>>>(
            V, w1T, b1v, FFN, DM, DM, DM, DFF,
            1, 0, 0, 0, 0, 0, 0, 0, 1);
        mma_nth16<<<dim3(DM / 128, rows / 64, 1), 128>>>(
            FFN, w2T, b2v, TMP, DFF, DFF, DFF, DM,
            1, 0, 0, 0, 0, 0, 0, 0, 0);
        ln_add<<<rows, 256>>>(V, TMP, lg + 4 * DM, lb + 4 * DM, V);

        mma_nth16<<<dim3(DFF / 128, rows / 64, 1), 128>>>(
            Q, w1T + (long long)DM * DFF, b1v + DFF, FFN, DM, DM, DM, DFF,
            1, 0, 0, 0, 0, 0, 0, 0, 1);
        mma_nth16<<<dim3(DM / 128, rows / 64, 1), 128>>>(
            FFN, w2T + (long long)DFF * DM, b2v + DM, TMP, DFF, DFF, DFF, DM,
            1, 0, 0, 0, 0, 0, 0, 0, 0);
        ln_add<<<rows, 256>>>(Q, TMP, lg + 5 * DM, lb + 5 * DM, Q);
    }

    // Final bilinear attention pooling (fp32-B kernels).
    float* PQs = QKV;
    float* Ts  = QKV + NT;
    vmul_k<<<(NTOK + 255) / 256, 256>>>(V, att_w, PQs, NTOK);
    mma_nt2h<<<dim3(NS / 128, NS / 64, BB), 128>>>(
        PQs, Q, SC, DM, DM, DM, NS,
        1, SBATCH, 0, SBATCH, 0, (long long)NS * NS, 0, 1.0f);
    softmax_final<<<BB * NS, 256>>>(SC, v_mask, q_mask, att_b);
    mma_nn2h<<<dim3(DM / 128, NS / 64, BB), 128>>>(
        SC, Q, (const float*)nullptr, Ts, NS, NS, DM, DM,
        1, (long long)NS * NS, 0, SBATCH, 0, SBATCH, 0, 0, 0);
    final_out_k<<<BB, 512>>>(V, Ts, (float*)d_out);
}

// round 16
// speedup vs baseline: 1.1235x; 1.1235x over previous
#include <cuda_runtime.h>
#include <cuda_bf16.h>
#include <cuda_fp16.h>
#include <cstdint>

// ---------------------------------------------------------------------------
// CoAttention R15: paired batching of independent MHA/FFN halves + flash
// occupancy forced to 4 blocks/SM. fp16 pre-transposed weights (R14).
// ---------------------------------------------------------------------------

#define BB    8
#define NS    512
#define DM    512
#define NHEAD 8
#define DHH   64
#define DFF   2048
#define NLAY  4
#define LN_EPS 1e-5f

#define NTC (BB*NS*DM)          // elements per [B,N,D] tensor
#define NFF (BB*NS*DFF)

// ------------------------------- scratch -----------------------------------
__device__ float g_x  [2*NTC];      // V,Q pair (persistent states)
__device__ float g_xa [2*NTC];      // VA,QA pair
__device__ float g_qkv[6*NTC];      // paired QKV (2 attentions)
__device__ float g_ao [2*NTC];
__device__ float g_tmp[2*NTC];
__device__ float g_vq [NTC];
__device__ float g_qv [NTC];
__device__ float g_ffn[2*NFF];
__device__ float g_sc [BB*NS*NS];

// fp16 transposed weights ([out][in] per matrix)
__device__ __half h_attn_w [NLAY*4*3*DM*DM];
__device__ __half h_attn_wo[NLAY*4*DM*DM];
__device__ __half h_ffn_w1 [NLAY*2*(long long)DM*DFF];
__device__ __half h_ffn_w2 [NLAY*2*(long long)DFF*DM];

// ------------------------------- helpers -----------------------------------

__device__ __forceinline__ unsigned f2h2(float a, float b) {
    __half2 h = __floats2half2_rn(a, b);
    return *reinterpret_cast<unsigned*>(&h);
}

__device__ __forceinline__ void mma16816(float* c, const unsigned* a, const unsigned* b) {
    asm volatile(
        "mma.sync.aligned.m16n8k16.row.col.f32.f16.f16.f32 "
        "{%0,%1,%2,%3}, {%4,%5,%6,%7}, {%8,%9}, {%0,%1,%2,%3};\n"
        : "+f"(c[0]), "+f"(c[1]), "+f"(c[2]), "+f"(c[3])
        : "r"(a[0]), "r"(a[1]), "r"(a[2]), "r"(a[3]), "r"(b[0]), "r"(b[1]));
}

#define LDSM4(r0, r1, r2, r3, addr) \
    asm volatile("ldmatrix.sync.aligned.m8n8.x4.shared.b16 {%0,%1,%2,%3}, [%4];" \
        : "=r"(r0), "=r"(r1), "=r"(r2), "=r"(r3) : "r"(addr))

#define SH 40
#define ROWB 80
#define A2BUF (64  * ROWB)
#define B2BUF (128 * ROWB)

#define FA_KSTRB 144
#define FA_VSTRB 272

// ------------------------------- kernels -----------------------------------

__global__ void copy_k(const float* __restrict__ src, float* __restrict__ dst, int n) {
    int i = blockIdx.x * blockDim.x + threadIdx.x;
    if (i < n) dst[i] = src[i];
}

// transpose+convert: X fp32 [R][C] -> Y fp16 [C][R]; z = matrix index.
__global__ __launch_bounds__(256) void transpose_w(
    const float* __restrict__ X, __half* __restrict__ Y, int R, int C)
{
    long long mat = blockIdx.z;
    X += mat * (long long)R * C;
    Y += mat * (long long)R * C;
    __shared__ float t[32][33];
    int c0 = blockIdx.x * 32, r0 = blockIdx.y * 32;
    int tx = threadIdx.x, ty = threadIdx.y;
    #pragma unroll
    for (int j = 0; j < 32; j += 8)
        t[ty + j][tx] = X[(long long)(r0 + ty + j) * C + c0 + tx];
    __syncthreads();
    #pragma unroll
    for (int j = 0; j < 32; j += 8)
        Y[(long long)(c0 + ty + j) * R + r0 + tx] = __float2half_rn(t[tx][ty + j]);
}

// ======== weight GEMM: A fp32 [M,K], B fp16 pre-transposed [N,K] ===========
__global__ __launch_bounds__(128) void mma_nth16(
    const float* __restrict__ A, const __half* __restrict__ Bh,
    const float* __restrict__ bias, float* __restrict__ C,
    int K, int lda, int ldb, int ldc,
    int zdiv, long long sA1, long long sA2, long long sB1, long long sB2,
    long long sC1, long long sC2, long long sBias, int relu)
{
    int z = blockIdx.z;
    int z1 = z / zdiv, z2 = z - z1 * zdiv;
    A  += z1 * sA1 + (long long)z2 * sA2;
    Bh += z1 * sB1 + (long long)z2 * sB2;
    C  += z1 * sC1 + (long long)z2 * sC2;
    if (bias) bias += (long long)z * sBias;

    __shared__ __align__(16) __half As[2][64][SH];
    __shared__ __align__(16) __half Bs[2][128][SH];

    const int tid = threadIdx.x;
    const int wid = tid >> 5, lane = tid & 31;
    const int wm = (wid >> 1) * 32, wn = (wid & 1) * 64;
    const int g = lane >> 2, t4 = lane & 3;
    const int row0 = blockIdx.y * 64, col0 = blockIdx.x * 128;

    const int a_r = tid >> 1, a_kh = (tid & 1) * 16;
    const float* Aptr = A + (long long)(row0 + a_r) * lda + a_kh;

    const int lr = lane & 7, sel = lane >> 3;
    unsigned as0 = (unsigned)__cvta_generic_to_shared(&As[0][0][0]);
    unsigned bs0 = (unsigned)__cvta_generic_to_shared(&Bs[0][0][0]);
    unsigned aaddr = as0 + (unsigned)((wm + (sel & 1) * 8 + lr) * ROWB + (sel >> 1) * 16);
    unsigned baddr[4];
    #pragma unroll
    for (int j = 0; j < 4; j++)
        baddr[j] = bs0 + (unsigned)((wn + j * 16 + (sel >> 1) * 8 + lr) * ROWB + (sel & 1) * 16);

    float acc[2][8][4];
    #pragma unroll
    for (int mi = 0; mi < 2; mi++)
        #pragma unroll
        for (int ni = 0; ni < 8; ni++)
            #pragma unroll
            for (int r = 0; r < 4; r++) acc[mi][ni][r] = 0.f;

    {
        unsigned ah[8];
        uint4 bv[4];
        #pragma unroll
        for (int i = 0; i < 4; i++) {
            float4 v = *(const float4*)(Aptr + i * 4);
            ah[2 * i]     = f2h2(v.x, v.y);
            ah[2 * i + 1] = f2h2(v.z, v.w);
        }
        #pragma unroll
        for (int i = 0; i < 4; i++) {
            int lin = i * 128 + tid;
            int br = lin >> 2, bq = (lin & 3) * 8;
            bv[i] = *(const uint4*)(Bh + (long long)(col0 + br) * ldb + bq);
        }
        *(uint4*)(&As[0][a_r][a_kh])     = make_uint4(ah[0], ah[1], ah[2], ah[3]);
        *(uint4*)(&As[0][a_r][a_kh + 8]) = make_uint4(ah[4], ah[5], ah[6], ah[7]);
        #pragma unroll
        for (int i = 0; i < 4; i++) {
            int lin = i * 128 + tid;
            int br = lin >> 2, bq = (lin & 3) * 8;
            *(uint4*)(&Bs[0][br][bq]) = bv[i];
        }
    }
    __syncthreads();

    const int nk = K >> 5;
    for (int t = 0; t < nk; t++) {
        const int buf = t & 1;
        unsigned ah[8];
        uint4 bv[4];
        if (t + 1 < nk) {
            int k0 = (t + 1) << 5;
            #pragma unroll
            for (int i = 0; i < 4; i++) {
                float4 v = *(const float4*)(Aptr + k0 + i * 4);
                ah[2 * i]     = f2h2(v.x, v.y);
                ah[2 * i + 1] = f2h2(v.z, v.w);
            }
            #pragma unroll
            for (int i = 0; i < 4; i++) {
                int lin = i * 128 + tid;
                int br = lin >> 2, bq = (lin & 3) * 8;
                bv[i] = *(const uint4*)(Bh + (long long)(col0 + br) * ldb + k0 + bq);
            }
        }

        #pragma unroll
        for (int ks = 0; ks < 2; ks++) {
            unsigned ko = (unsigned)(ks * 32);
            unsigned ao = (unsigned)(buf * A2BUF) + ko;
            unsigned bo = (unsigned)(buf * B2BUF) + ko;
            unsigned af0[4], af1[4], bf[4][4];
            LDSM4(af0[0], af0[1], af0[2], af0[3], aaddr + ao);
            LDSM4(af1[0], af1[1], af1[2], af1[3], aaddr + 16u * ROWB + ao);
            #pragma unroll
            for (int j = 0; j < 4; j++)
                LDSM4(bf[j][0], bf[j][1], bf[j][2], bf[j][3], baddr[j] + bo);
            #pragma unroll
            for (int j = 0; j < 4; j++) {
                mma16816(acc[0][2 * j],     af0, &bf[j][0]);
                mma16816(acc[0][2 * j + 1], af0, &bf[j][2]);
                mma16816(acc[1][2 * j],     af1, &bf[j][0]);
                mma16816(acc[1][2 * j + 1], af1, &bf[j][2]);
            }
        }

        if (t + 1 < nk) {
            const int nb = (t + 1) & 1;
            *(uint4*)(&As[nb][a_r][a_kh])     = make_uint4(ah[0], ah[1], ah[2], ah[3]);
            *(uint4*)(&As[nb][a_r][a_kh + 8]) = make_uint4(ah[4], ah[5], ah[6], ah[7]);
            #pragma unroll
            for (int i = 0; i < 4; i++) {
                int lin = i * 128 + tid;
                int br = lin >> 2, bq = (lin & 3) * 8;
                *(uint4*)(&Bs[nb][br][bq]) = bv[i];
            }
            __syncthreads();
        }
    }

    #pragma unroll
    for (int mi = 0; mi < 2; mi++)
        #pragma unroll
        for (int ni = 0; ni < 8; ni++) {
            int r = row0 + wm + mi * 16 + g;
            int c = col0 + wn + ni * 8 + 2 * t4;
            float b0v = 0.f, b1v = 0.f;
            if (bias) { b0v = bias[c]; b1v = bias[c + 1]; }
            float o0 = acc[mi][ni][0] + b0v;
            float o1 = acc[mi][ni][1] + b1v;
            float o2 = acc[mi][ni][2] + b0v;
            float o3 = acc[mi][ni][3] + b1v;
            if (relu) {
                o0 = fmaxf(o0, 0.f); o1 = fmaxf(o1, 0.f);
                o2 = fmaxf(o2, 0.f); o3 = fmaxf(o3, 0.f);
            }
            *(float2*)(C + (long long)r * ldc + c)       = make_float2(o0, o1);
            *(float2*)(C + (long long)(r + 8) * ldc + c) = make_float2(o2, o3);
        }
}

// ======== NN GEMM fp32-B (final bilinear: SC @ Q) ==========================
__global__ __launch_bounds__(128) void mma_nn2h(
    const float* __restrict__ A, const float* __restrict__ B,
    const float* __restrict__ bias, float* __restrict__ C,
    int K, int lda, int ldb, int ldc,
    int zdiv, long long sA1, long long sA2, long long sB1, long long sB2,
    long long sC1, long long sC2, long long sBias, int relu)
{
    int z = blockIdx.z;
    int z1 = z / zdiv, z2 = z - z1 * zdiv;
    A += z1 * sA1 + (long long)z2 * sA2;
    B += z1 * sB1 + (long long)z2 * sB2;
    C += z1 * sC1 + (long long)z2 * sC2;
    if (bias) bias += (long long)z * sBias;

    __shared__ __align__(16) __half As[2][64][SH];
    __shared__ __align__(16) __half Bs[2][128][SH];

    const int tid = threadIdx.x;
    const int wid = tid >> 5, lane = tid & 31;
    const int wm = (wid >> 1) * 32, wn = (wid & 1) * 64;
    const int g = lane >> 2, t4 = lane & 3;
    const int row0 = blockIdx.y * 64, col0 = blockIdx.x * 128;

    const int a_r = tid >> 1, a_kh = (tid & 1) * 16;
    const float* Aptr = A + (long long)(row0 + a_r) * lda + a_kh;
    const float* Bptr = B + col0 + tid;

    const int lr = lane & 7, sel = lane >> 3;
    unsigned as0 = (unsigned)__cvta_generic_to_shared(&As[0][0][0]);
    unsigned bs0 = (unsigned)__cvta_generic_to_shared(&Bs[0][0][0]);
    unsigned aaddr = as0 + (unsigned)((wm + (sel & 1) * 8 + lr) * ROWB + (sel >> 1) * 16);
    unsigned baddr[4];
    #pragma unroll
    for (int j = 0; j < 4; j++)
        baddr[j] = bs0 + (unsigned)((wn + j * 16 + (sel >> 1) * 8 + lr) * ROWB + (sel & 1) * 16);

    float acc[2][8][4];
    #pragma unroll
    for (int mi = 0; mi < 2; mi++)
        #pragma unroll
        for (int ni = 0; ni < 8; ni++)
            #pragma unroll
            for (int r = 0; r < 4; r++) acc[mi][ni][r] = 0.f;

    {
        unsigned ah[8], bh[16];
        #pragma unroll
        for (int i = 0; i < 4; i++) {
            float4 v = *(const float4*)(Aptr + i * 4);
            ah[2 * i]     = f2h2(v.x, v.y);
            ah[2 * i + 1] = f2h2(v.z, v.w);
        }
        #pragma unroll
        for (int j = 0; j < 16; j++)
            bh[j] = f2h2(Bptr[(long long)(2 * j) * ldb], Bptr[(long long)(2 * j + 1) * ldb]);
        *(uint4*)(&As[0][a_r][a_kh])     = make_uint4(ah[0], ah[1], ah[2], ah[3]);
        *(uint4*)(&As[0][a_r][a_kh + 8]) = make_uint4(ah[4], ah[5], ah[6], ah[7]);
        *(uint4*)(&Bs[0][tid][0])  = make_uint4(bh[0],  bh[1],  bh[2],  bh[3]);
        *(uint4*)(&Bs[0][tid][8])  = make_uint4(bh[4],  bh[5],  bh[6],  bh[7]);
        *(uint4*)(&Bs[0][tid][16]) = make_uint4(bh[8],  bh[9],  bh[10], bh[11]);
        *(uint4*)(&Bs[0][tid][24]) = make_uint4(bh[12], bh[13], bh[14], bh[15]);
    }
    __syncthreads();

    const int nk = K >> 5;
    for (int t = 0; t < nk; t++) {
        const int buf = t & 1;
        unsigned ah[8], bh[16];
        if (t + 1 < nk) {
            int k0 = (t + 1) << 5;
            #pragma unroll
            for (int i = 0; i < 4; i++) {
                float4 v = *(const float4*)(Aptr + k0 + i * 4);
                ah[2 * i]     = f2h2(v.x, v.y);
                ah[2 * i + 1] = f2h2(v.z, v.w);
            }
            #pragma unroll
            for (int j = 0; j < 16; j++)
                bh[j] = f2h2(Bptr[(long long)(k0 + 2 * j) * ldb],
                             Bptr[(long long)(k0 + 2 * j + 1) * ldb]);
        }

        #pragma unroll
        for (int ks = 0; ks < 2; ks++) {
            unsigned ko = (unsigned)(ks * 32);
            unsigned ao = (unsigned)(buf * A2BUF) + ko;
            unsigned bo = (unsigned)(buf * B2BUF) + ko;
            unsigned af0[4], af1[4], bf[4][4];
            LDSM4(af0[0], af0[1], af0[2], af0[3], aaddr + ao);
            LDSM4(af1[0], af1[1], af1[2], af1[3], aaddr + 16u * ROWB + ao);
            #pragma unroll
            for (int j = 0; j < 4; j++)
                LDSM4(bf[j][0], bf[j][1], bf[j][2], bf[j][3], baddr[j] + bo);
            #pragma unroll
            for (int j = 0; j < 4; j++) {
                mma16816(acc[0][2 * j],     af0, &bf[j][0]);
                mma16816(acc[0][2 * j + 1], af0, &bf[j][2]);
                mma16816(acc[1][2 * j],     af1, &bf[j][0]);
                mma16816(acc[1][2 * j + 1], af1, &bf[j][2]);
            }
        }

        if (t + 1 < nk) {
            const int nb = (t + 1) & 1;
            *(uint4*)(&As[nb][a_r][a_kh])     = make_uint4(ah[0], ah[1], ah[2], ah[3]);
            *(uint4*)(&As[nb][a_r][a_kh + 8]) = make_uint4(ah[4], ah[5], ah[6], ah[7]);
            *(uint4*)(&Bs[nb][tid][0])  = make_uint4(bh[0],  bh[1],  bh[2],  bh[3]);
            *(uint4*)(&Bs[nb][tid][8])  = make_uint4(bh[4],  bh[5],  bh[6],  bh[7]);
            *(uint4*)(&Bs[nb][tid][16]) = make_uint4(bh[8],  bh[9],  bh[10], bh[11]);
            *(uint4*)(&Bs[nb][tid][24]) = make_uint4(bh[12], bh[13], bh[14], bh[15]);
            __syncthreads();
        }
    }

    #pragma unroll
    for (int mi = 0; mi < 2; mi++)
        #pragma unroll
        for (int ni = 0; ni < 8; ni++) {
            int r = row0 + wm + mi * 16 + g;
            int c = col0 + wn + ni * 8 + 2 * t4;
            float b0v = 0.f, b1v = 0.f;
            if (bias) { b0v = bias[c]; b1v = bias[c + 1]; }
            float o0 = acc[mi][ni][0] + b0v;
            float o1 = acc[mi][ni][1] + b1v;
            float o2 = acc[mi][ni][2] + b0v;
            float o3 = acc[mi][ni][3] + b1v;
            if (relu) {
                o0 = fmaxf(o0, 0.f); o1 = fmaxf(o1, 0.f);
                o2 = fmaxf(o2, 0.f); o3 = fmaxf(o3, 0.f);
            }
            *(float2*)(C + (long long)r * ldc + c)       = make_float2(o0, o1);
            *(float2*)(C + (long long)(r + 8) * ldc + c) = make_float2(o2, o3);
        }
}

// ======== NT GEMM fp32-B (final bilinear: PQs @ Q^T) =======================
__global__ __launch_bounds__(128) void mma_nt2h(
    const float* __restrict__ A, const float* __restrict__ B,
    float* __restrict__ C,
    int K, int lda, int ldb, int ldc,
    int zdiv, long long sA1, long long sA2, long long sB1, long long sB2,
    long long sC1, long long sC2, float scale)
{
    int z = blockIdx.z;
    int z1 = z / zdiv, z2 = z - z1 * zdiv;
    A += z1 * sA1 + (long long)z2 * sA2;
    B += z1 * sB1 + (long long)z2 * sB2;
    C += z1 * sC1 + (long long)z2 * sC2;

    __shared__ __align__(16) __half As[2][64][SH];
    __shared__ __align__(16) __half Bs[2][128][SH];

    const int tid = threadIdx.x;
    const int wid = tid >> 5, lane = tid & 31;
    const int wm = (wid >> 1) * 32, wn = (wid & 1) * 64;
    const int g = lane >> 2, t4 = lane & 3;
    const int row0 = blockIdx.y * 64, col0 = blockIdx.x * 128;

    const int a_r = tid >> 1, a_kh = (tid & 1) * 16;
    const float* Aptr = A + (long long)(row0 + a_r) * lda + a_kh;
    const float* Bptr = B + (long long)(col0 + tid) * ldb;

    const int lr = lane & 7, sel = lane >> 3;
    unsigned as0 = (unsigned)__cvta_generic_to_shared(&As[0][0][0]);
    unsigned bs0 = (unsigned)__cvta_generic_to_shared(&Bs[0][0][0]);
    unsigned aaddr = as0 + (unsigned)((wm + (sel & 1) * 8 + lr) * ROWB + (sel >> 1) * 16);
    unsigned baddr[4];
    #pragma unroll
    for (int j = 0; j < 4; j++)
        baddr[j] = bs0 + (unsigned)((wn + j * 16 + (sel >> 1) * 8 + lr) * ROWB + (sel & 1) * 16);

    float acc[2][8][4];
    #pragma unroll
    for (int mi = 0; mi < 2; mi++)
        #pragma unroll
        for (int ni = 0; ni < 8; ni++)
            #pragma unroll
            for (int r = 0; r < 4; r++) acc[mi][ni][r] = 0.f;

    {
        unsigned ah[8], bh[16];
        #pragma unroll
        for (int i = 0; i < 4; i++) {
            float4 v = *(const float4*)(Aptr + i * 4);
            ah[2 * i]     = f2h2(v.x, v.y);
            ah[2 * i + 1] = f2h2(v.z, v.w);
        }
        #pragma unroll
        for (int i = 0; i < 8; i++) {
            float4 v = *(const float4*)(Bptr + i * 4);
            bh[2 * i]     = f2h2(v.x, v.y);
            bh[2 * i + 1] = f2h2(v.z, v.w);
        }
        *(uint4*)(&As[0][a_r][a_kh])     = make_uint4(ah[0], ah[1], ah[2], ah[3]);
        *(uint4*)(&As[0][a_r][a_kh + 8]) = make_uint4(ah[4], ah[5], ah[6], ah[7]);
        *(uint4*)(&Bs[0][tid][0])  = make_uint4(bh[0],  bh[1],  bh[2],  bh[3]);
        *(uint4*)(&Bs[0][tid][8])  = make_uint4(bh[4],  bh[5],  bh[6],  bh[7]);
        *(uint4*)(&Bs[0][tid][16]) = make_uint4(bh[8],  bh[9],  bh[10], bh[11]);
        *(uint4*)(&Bs[0][tid][24]) = make_uint4(bh[12], bh[13], bh[14], bh[15]);
    }
    __syncthreads();

    const int nk = K >> 5;
    for (int t = 0; t < nk; t++) {
        const int buf = t & 1;
        unsigned ah[8], bh[16];
        if (t + 1 < nk) {
            int k0 = (t + 1) << 5;
            #pragma unroll
            for (int i = 0; i < 4; i++) {
                float4 v = *(const float4*)(Aptr + k0 + i * 4);
                ah[2 * i]     = f2h2(v.x, v.y);
                ah[2 * i + 1] = f2h2(v.z, v.w);
            }
            #pragma unroll
            for (int i = 0; i < 8; i++) {
                float4 v = *(const float4*)(Bptr + k0 + i * 4);
                bh[2 * i]     = f2h2(v.x, v.y);
                bh[2 * i + 1] = f2h2(v.z, v.w);
            }
        }

        #pragma unroll
        for (int ks = 0; ks < 2; ks++) {
            unsigned ko = (unsigned)(ks * 32);
            unsigned ao = (unsigned)(buf * A2BUF) + ko;
            unsigned bo = (unsigned)(buf * B2BUF) + ko;
            unsigned af0[4], af1[4], bf[4][4];
            LDSM4(af0[0], af0[1], af0[2], af0[3], aaddr + ao);
            LDSM4(af1[0], af1[1], af1[2], af1[3], aaddr + 16u * ROWB + ao);
            #pragma unroll
            for (int j = 0; j < 4; j++)
                LDSM4(bf[j][0], bf[j][1], bf[j][2], bf[j][3], baddr[j] + bo);
            #pragma unroll
            for (int j = 0; j < 4; j++) {
                mma16816(acc[0][2 * j],     af0, &bf[j][0]);
                mma16816(acc[0][2 * j + 1], af0, &bf[j][2]);
                mma16816(acc[1][2 * j],     af1, &bf[j][0]);
                mma16816(acc[1][2 * j + 1], af1, &bf[j][2]);
            }
        }

        if (t + 1 < nk) {
            const int nb = (t + 1) & 1;
            *(uint4*)(&As[nb][a_r][a_kh])     = make_uint4(ah[0], ah[1], ah[2], ah[3]);
            *(uint4*)(&As[nb][a_r][a_kh + 8]) = make_uint4(ah[4], ah[5], ah[6], ah[7]);
            *(uint4*)(&Bs[nb][tid][0])  = make_uint4(bh[0],  bh[1],  bh[2],  bh[3]);
            *(uint4*)(&Bs[nb][tid][8])  = make_uint4(bh[4],  bh[5],  bh[6],  bh[7]);
            *(uint4*)(&Bs[nb][tid][16]) = make_uint4(bh[8],  bh[9],  bh[10], bh[11]);
            *(uint4*)(&Bs[nb][tid][24]) = make_uint4(bh[12], bh[13], bh[14], bh[15]);
            __syncthreads();
        }
    }

    #pragma unroll
    for (int mi = 0; mi < 2; mi++)
        #pragma unroll
        for (int ni = 0; ni < 8; ni++) {
            int r = row0 + wm + mi * 16 + g;
            int c = col0 + wn + ni * 8 + 2 * t4;
            *(float2*)(C + (long long)r * ldc + c) =
                make_float2(acc[mi][ni][0] * scale, acc[mi][ni][1] * scale);
            *(float2*)(C + (long long)(r + 8) * ldc + c) =
                make_float2(acc[mi][ni][2] * scale, acc[mi][ni][3] * scale);
        }
}

// ======== fused flash attention (supports 1 or 2 batched attentions) =======
// grid (NS/64, nAtt*64), 128 threads, forced 4 blocks/SM.
// QKV layout: [att][3][B,N,D]; Og: [att][B,N,D]; mask0 for att0, mask1 att1.
__global__ __launch_bounds__(128, 4) void flash_attn(
    const float* __restrict__ QKV, const int* __restrict__ mask0,
    const int* __restrict__ mask1, float* __restrict__ Og)
{
    __shared__ __align__(16) __half Qs[64 * (FA_KSTRB / 2)];
    __shared__ __align__(16) __half Ks[128 * (FA_KSTRB / 2)];
    __shared__ __align__(16) __half Vs[64 * (FA_VSTRB / 2)];
    __shared__ float msk[NS];

    const int a  = blockIdx.y >> 6;
    const int bh = blockIdx.y & 63;
    const int b = bh >> 3, h = bh & 7;
    const int q0 = blockIdx.x * 64;
    const int* mask = a ? mask1 : mask0;
    const float* Qg = QKV + (long long)a * 3 * NTC;
    const float* Qp = Qg + (long long)b * NS * DM + h * DHH;
    const float* Kp = Qp + NTC;
    const float* Vp = Qp + 2 * NTC;
    float* Ob = Og + (long long)a * NTC;

    const int tid = threadIdx.x;
    const int wid = tid >> 5, lane = tid & 31;
    const int g = lane >> 2, t4 = lane & 3;
    const int lr = lane & 7, sel = lane >> 3;

    unsigned qs_b = (unsigned)__cvta_generic_to_shared(Qs);
    unsigned ks_b = (unsigned)__cvta_generic_to_shared(Ks);
    unsigned vs_b = (unsigned)__cvta_generic_to_shared(Vs);

    for (int j = tid; j < NS; j += 128)
        msk[j] = mask[b * NS + j] ? 0.f : -1e9f;

    {
        int r = tid >> 1, kh = (tid & 1) * 32;
        const float* qp = Qp + (long long)(q0 + r) * DM + kh;
        __half* dst = Qs + r * (FA_KSTRB / 2) + kh;
        #pragma unroll
        for (int i = 0; i < 8; i++) {
            float4 v = *(const float4*)(qp + i * 4);
            *(uint2*)(dst + i * 4) = make_uint2(f2h2(v.x, v.y), f2h2(v.z, v.w));
        }
    }

    unsigned qa = qs_b + (unsigned)((wid * 16 + (sel & 1) * 8 + lr) * FA_KSTRB + (sel >> 1) * 16);

    float m0 = -1e30f, m1 = -1e30f, l0 = 0.f, l1 = 0.f;
    float o[8][4];
    #pragma unroll
    for (int p = 0; p < 8; p++)
        #pragma unroll
        for (int r = 0; r < 4; r++) o[p][r] = 0.f;

    for (int c = 0; c < 4; c++) {
        const int j0 = c * 128;
        {
            const float* kp = Kp + (long long)(j0 + tid) * DM;
            __half* dst = Ks + tid * (FA_KSTRB / 2);
            #pragma unroll
            for (int i = 0; i < 16; i++) {
                float4 v = *(const float4*)(kp + i * 4);
                *(uint2*)(dst + i * 4) = make_uint2(f2h2(v.x, v.y), f2h2(v.z, v.w));
            }
            const float* vp = Vp + (long long)(j0 + tid) * DM;
            __half* base = Vs + tid;
            #pragma unroll
            for (int i = 0; i < 16; i++) {
                float4 v = *(const float4*)(vp + i * 4);
                base[(4 * i + 0) * (FA_VSTRB / 2)] = __float2half_rn(v.x);
                base[(4 * i + 1) * (FA_VSTRB / 2)] = __float2half_rn(v.y);
                base[(4 * i + 2) * (FA_VSTRB / 2)] = __float2half_rn(v.z);
                base[(4 * i + 3) * (FA_VSTRB / 2)] = __float2half_rn(v.w);
            }
        }
        __syncthreads();

        float s[16][4];
        #pragma unroll
        for (int p = 0; p < 16; p++)
            #pragma unroll
            for (int r = 0; r < 4; r++) s[p][r] = 0.f;

        #pragma unroll
        for (int ks = 0; ks < 4; ks++) {
            unsigned af[4];
            LDSM4(af[0], af[1], af[2], af[3], qa + ks * 32);
            #pragma unroll
            for (int p = 0; p < 8; p++) {
                unsigned bf[4];
                unsigned ba = ks_b + (unsigned)((p * 16 + (sel >> 1) * 8 + lr) * FA_KSTRB
                                                + (sel & 1) * 16) + ks * 32;
                LDSM4(bf[0], bf[1], bf[2], bf[3], ba);
                mma16816(s[2 * p],     af, &bf[0]);
                mma16816(s[2 * p + 1], af, &bf[2]);
            }
        }

        float cm0 = -1e30f, cm1 = -1e30f;
        #pragma unroll
        for (int p = 0; p < 16; p++) {
            int col = j0 + p * 8 + 2 * t4;
            float mv0 = msk[col], mv1 = msk[col + 1];
            s[p][0] = s[p][0] * 0.125f + mv0;
            s[p][1] = s[p][1] * 0.125f + mv1;
            s[p][2] = s[p][2] * 0.125f + mv0;
            s[p][3] = s[p][3] * 0.125f + mv1;
            cm0 = fmaxf(cm0, fmaxf(s[p][0], s[p][1]));
            cm1 = fmaxf(cm1, fmaxf(s[p][2], s[p][3]));
        }
        cm0 = fmaxf(cm0, __shfl_xor_sync(0xffffffffu, cm0, 1));
        cm0 = fmaxf(cm0, __shfl_xor_sync(0xffffffffu, cm0, 2));
        cm1 = fmaxf(cm1, __shfl_xor_sync(0xffffffffu, cm1, 1));
        cm1 = fmaxf(cm1, __shfl_xor_sync(0xffffffffu, cm1, 2));

        float nm0 = fmaxf(m0, cm0), nm1 = fmaxf(m1, cm1);
        float sc0 = __expf(m0 - nm0), sc1 = __expf(m1 - nm1);
        m0 = nm0; m1 = nm1;
        l0 *= sc0; l1 *= sc1;
        #pragma unroll
        for (int p = 0; p < 8; p++) {
            o[p][0] *= sc0; o[p][1] *= sc0;
            o[p][2] *= sc1; o[p][3] *= sc1;
        }

        #pragma unroll
        for (int p = 0; p < 16; p++) {
            s[p][0] = __expf(s[p][0] - m0);
            s[p][1] = __expf(s[p][1] - m0);
            s[p][2] = __expf(s[p][2] - m1);
            s[p][3] = __expf(s[p][3] - m1);
            l0 += s[p][0] + s[p][1];
            l1 += s[p][2] + s[p][3];
        }

        #pragma unroll
        for (int p = 0; p < 8; p++) {
            unsigned af[4];
            af[0] = f2h2(s[2 * p][0],     s[2 * p][1]);
            af[1] = f2h2(s[2 * p][2],     s[2 * p][3]);
            af[2] = f2h2(s[2 * p + 1][0], s[2 * p + 1][1]);
            af[3] = f2h2(s[2 * p + 1][2], s[2 * p + 1][3]);
            #pragma unroll
            for (int n = 0; n < 4; n++) {
                unsigned bf[4];
                unsigned ba = vs_b + (unsigned)((n * 16 + (sel >> 1) * 8 + lr) * FA_VSTRB
                                                + ((sel & 1) * 8 + p * 16) * 2);
                LDSM4(bf[0], bf[1], bf[2], bf[3], ba);
                mma16816(o[2 * n],     af, &bf[0]);
                mma16816(o[2 * n + 1], af, &bf[2]);
            }
        }
        __syncthreads();
    }

    l0 += __shfl_xor_sync(0xffffffffu, l0, 1);
    l0 += __shfl_xor_sync(0xffffffffu, l0, 2);
    l1 += __shfl_xor_sync(0xffffffffu, l1, 1);
    l1 += __shfl_xor_sync(0xffffffffu, l1, 2);
    const float inv0 = 1.f / l0, inv1 = 1.f / l1;

    {
        int r0 = q0 + wid * 16 + g;
        float* out0 = Ob + ((long long)b * NS + r0) * DM + h * DHH;
        float* out1 = out0 + 8ll * DM;
        #pragma unroll
        for (int p = 0; p < 8; p++) {
            int cc = p * 8 + 2 * t4;
            *(float2*)(out0 + cc) = make_float2(o[p][0] * inv0, o[p][1] * inv0);
            *(float2*)(out1 + cc) = make_float2(o[p][2] * inv1, o[p][3] * inv1);
        }
    }
}

// out[row] = LN(x[row] + y[row]) * g + b.
__global__ __launch_bounds__(256) void ln_add(
    const float* __restrict__ X, const float* __restrict__ Y,
    const float* __restrict__ g, const float* __restrict__ be,
    float* __restrict__ O)
{
    int row = blockIdx.x;
    const float* xp = X + (long long)row * DM;
    const float* yp = Y + (long long)row * DM;
    float* op = O + (long long)row * DM;
    int tid = threadIdx.x;

    float a0 = xp[tid] + yp[tid];
    float a1 = xp[tid + 256] + yp[tid + 256];

    __shared__ float r1[256];
    __shared__ float r2[256];
    r1[tid] = a0 + a1;
    r2[tid] = a0 * a0 + a1 * a1;
    __syncthreads();
    for (int s = 128; s > 0; s >>= 1) {
        if (tid < s) { r1[tid] += r1[tid + s]; r2[tid] += r2[tid + s]; }
        __syncthreads();
    }
    float mean = r1[0] * (1.f / DM);
    float var  = r2[0] * (1.f / DM) - mean * mean;
    float rstd = rsqrtf(var + LN_EPS);
    op[tid]       = (a0 - mean) * rstd * g[tid]       + be[tid];
    op[tid + 256] = (a1 - mean) * rstd * g[tid + 256] + be[tid + 256];
}

__global__ void vmul_k(const float* __restrict__ v, const float* __restrict__ w,
                       float* __restrict__ o, int n) {
    int i = blockIdx.x * blockDim.x + threadIdx.x;
    if (i < n) o[i] = v[i] * w[i & (DM - 1)];
}

__global__ __launch_bounds__(256) void softmax_final(
    float* __restrict__ S, const int* __restrict__ vmask,
    const int* __restrict__ qmask, const float* __restrict__ attb)
{
    int row = blockIdx.x;
    int b = row >> 9, i = row & (NS - 1);
    int rowpad = (vmask[b * NS + i] == 0);
    float ab = attb[0];
    float* Sp = S + (long long)row * NS;
    int tid = threadIdx.x;

    float v0 = (rowpad || qmask[b * NS + tid] == 0)       ? -1e9f : Sp[tid] + ab;
    float v1 = (rowpad || qmask[b * NS + tid + 256] == 0) ? -1e9f : Sp[tid + 256] + ab;

    __shared__ float red[256];
    red[tid] = fmaxf(v0, v1);
    __syncthreads();
    for (int s = 128; s > 0; s >>= 1) {
        if (tid < s) red[tid] = fmaxf(red[tid], red[tid + s]);
        __syncthreads();
    }
    float m = red[0];
    __syncthreads();

    float e0 = __expf(v0 - m), e1 = __expf(v1 - m);
    red[tid] = e0 + e1;
    __syncthreads();
    for (int s = 128; s > 0; s >>= 1) {
        if (tid < s) red[tid] += red[tid + s];
        __syncthreads();
    }
    float inv = 1.f / red[0];
    Sp[tid]       = e0 * inv;
    Sp[tid + 256] = e1 * inv;
}

__global__ void final_out_k(const float* __restrict__ V, const float* __restrict__ T,
                            float* __restrict__ out) {
    int b = blockIdx.x;
    int k = threadIdx.x;
    const float* vp = V + (long long)b * NS * DM;
    const float* tp = T + (long long)b * NS * DM;
    float acc = 0.f;
    #pragma unroll 4
    for (int i = 0; i < NS; i++)
        acc = fmaf(vp[(long long)i * DM + k], tp[(long long)i * DM + k], acc);
    out[b * DM + k] = acc * (1.f / 512.f);
}

// ------------------------------- host side ---------------------------------

// single (cross) MHA: xq -> queries, xkv -> keys/values, result in out.
static void run_mha1(const float* xq, const float* xkv, const int* mask,
                     const __half* wT, const float* b,
                     const __half* woT, const float* bo,
                     float* QKV, float* AO, float* out)
{
    const long long WS = (long long)DM * DM;
    const dim3 gP(DM / 128, (BB * NS) / 64, 1);

    mma_nth16<<<gP, 128>>>(
        xq, wT, b, QKV, DM, DM, DM, DM,
        1, 0, 0, 0, 0, 0, 0, DM, 0);
    mma_nth16<<<dim3(DM / 128, (BB * NS) / 64, 2), 128>>>(
        xkv, wT + WS, b + DM, QKV + NTC, DM, DM, DM, DM,
        2, 0, 0, 0, WS, 0, (long long)NTC, DM, 0);

    flash_attn<<<dim3(NS / 64, 64), 128>>>(QKV, mask, mask, AO);

    mma_nth16<<<gP, 128>>>(
        AO, woT, bo, out, DM, DM, DM, DM,
        1, 0, 0, 0, 0, 0, 0, DM, 0);
}

extern "C" void kernel_launch(void* const* d_in, const int* in_sizes, int n_in,
                              void* d_out, int out_size)
{
    const float *v_in, *q_in, *attn_w, *attn_b, *attn_wo, *attn_bo;
    const float *ln_g, *ln_b, *fw1, *fb1, *fw2, *fb2, *att_w, *att_b;
    const int *v_mask, *q_mask;

    if (in_sizes[2] == BB * NS) {   // dict order
        v_in    = (const float*)d_in[0];
        q_in    = (const float*)d_in[1];
        v_mask  = (const int*)  d_in[2];
        q_mask  = (const int*)  d_in[3];
        attn_w  = (const float*)d_in[4];
        attn_b  = (const float*)d_in[5];
        attn_wo = (const float*)d_in[6];
        attn_bo = (const float*)d_in[7];
        ln_g    = (const float*)d_in[8];
        ln_b    = (const float*)d_in[9];
        fw1     = (const float*)d_in[10];
        fb1     = (const float*)d_in[11];
        fw2     = (const float*)d_in[12];
        fb2     = (const float*)d_in[13];
        att_w   = (const float*)d_in[14];
        att_b   = (const float*)d_in[15];
    } else {                        // signature order
        v_in    = (const float*)d_in[0];
        q_in    = (const float*)d_in[1];
        attn_w  = (const float*)d_in[2];
        attn_b  = (const float*)d_in[3];
        attn_wo = (const float*)d_in[4];
        attn_bo = (const float*)d_in[5];
        ln_g    = (const float*)d_in[6];
        ln_b    = (const float*)d_in[7];
        fw1     = (const float*)d_in[8];
        fb1     = (const float*)d_in[9];
        fw2     = (const float*)d_in[10];
        fb2     = (const float*)d_in[11];
        att_w   = (const float*)d_in[12];
        att_b   = (const float*)d_in[13];
        v_mask  = (const int*)  d_in[14];
        q_mask  = (const int*)  d_in[15];
    }

    float *X, *XA, *QKV, *AO, *TMP, *VQ, *QV, *FFN, *SC;
    __half *HW, *HWO, *HF1, *HF2;
    cudaGetSymbolAddress((void**)&X,   g_x);
    cudaGetSymbolAddress((void**)&XA,  g_xa);
    cudaGetSymbolAddress((void**)&QKV, g_qkv);
    cudaGetSymbolAddress((void**)&AO,  g_ao);
    cudaGetSymbolAddress((void**)&TMP, g_tmp);
    cudaGetSymbolAddress((void**)&VQ,  g_vq);
    cudaGetSymbolAddress((void**)&QV,  g_qv);
    cudaGetSymbolAddress((void**)&FFN, g_ffn);
    cudaGetSymbolAddress((void**)&SC,  g_sc);
    cudaGetSymbolAddress((void**)&HW,  h_attn_w);
    cudaGetSymbolAddress((void**)&HWO, h_attn_wo);
    cudaGetSymbolAddress((void**)&HF1, h_ffn_w1);
    cudaGetSymbolAddress((void**)&HF2, h_ffn_w2);

    float* Xv = X;               // V state
    float* Xq = X + NTC;         // Q state

    const long long WS = (long long)DM * DM;
    const long long SBATCH = (long long)NS * DM;
    const int rows = BB * NS;

    // weight pre-transpose + fp16 conversion
    dim3 tb(32, 8, 1);
    transpose_w<<<dim3(DM / 32, DM / 32, NLAY * 4 * 3), tb>>>(attn_w,  HW,  DM, DM);
    transpose_w<<<dim3(DM / 32, DM / 32, NLAY * 4),     tb>>>(attn_wo, HWO, DM, DM);
    transpose_w<<<dim3(DFF / 32, DM / 32, NLAY * 2),    tb>>>(fw1, HF1, DM, DFF);
    transpose_w<<<dim3(DM / 32, DFF / 32, NLAY * 2),    tb>>>(fw2, HF2, DFF, DM);

    copy_k<<<(NTC + 255) / 256, 256>>>(v_in, Xv, NTC);
    copy_k<<<(NTC + 255) / 256, 256>>>(q_in, Xq, NTC);

    for (int i = 0; i < NLAY; i++) {
        const __half* wT  = HW  + (long long)i * 4 * 3 * WS;
        const __half* woT = HWO + (long long)i * 4 * WS;
        const float* ab  = attn_b  + (long long)i * 4 * 3 * DM;
        const float* abo = attn_bo + (long long)i * 4 * DM;
        const float* lg  = ln_g + (long long)i * 6 * DM;
        const float* lb  = ln_b + (long long)i * 6 * DM;

        // --- paired self-attention (V-self = att0, Q-self = att1) ---
        // QKV proj: z = a*3 + (q/k/v); A = X pair, B = wT[ a*3 + j ]
        mma_nth16<<<dim3(DM / 128, rows / 64, 6), 128>>>(
            X, wT, ab, QKV, DM, DM, DM, DM,
            3, (long long)NTC, 0, 3 * WS, WS, 3ll * NTC, (long long)NTC, DM, 0);
        flash_attn<<<dim3(NS / 64, 128), 128>>>(QKV, v_mask, q_mask, AO);
        // out proj pair: z = a; weights woT[0], woT[1]
        mma_nth16<<<dim3(DM / 128, rows / 64, 2), 128>>>(
            AO, woT, abo, TMP, DM, DM, DM, DM,
            2, 0, (long long)NTC, 0, WS, 0, (long long)NTC, DM, 0);

        ln_add<<<rows, 256>>>(Xv, TMP,       lg,      lb,      XA);        // VA
        ln_add<<<rows, 256>>>(Xq, TMP + NTC, lg + DM, lb + DM, XA + NTC);  // QA

        // --- cross attentions (sequential dependency) ---
        run_mha1(XA, XA + NTC, q_mask,
                 wT + 6 * WS, ab + 6 * DM, woT + 2 * WS, abo + 2 * DM,
                 QKV, AO, VQ);
        run_mha1(XA + NTC, VQ, v_mask,
                 wT + 9 * WS, ab + 9 * DM, woT + 3 * WS, abo + 3 * DM,
                 QKV, AO, QV);

        ln_add<<<rows, 256>>>(Xv, VQ, lg + 2 * DM, lb + 2 * DM, Xv);
        ln_add<<<rows, 256>>>(Xq, QV, lg + 3 * DM, lb + 3 * DM, Xq);

        // --- paired FFN ---
        const __half* w1T = HF1 + (long long)i * 2 * DM * DFF;   // [DFF][DM] x2
        const __half* w2T = HF2 + (long long)i * 2 * DFF * DM;   // [DM][DFF] x2
        const float* b1v = fb1 + (long long)i * 2 * DFF;
        const float* b2v = fb2 + (long long)i * 2 * DM;

        mma_nth16<<<dim3(DFF / 128, rows / 64, 2), 128>>>(
            X, w1T, b1v, FFN, DM, DM, DM, DFF,
            2, 0, (long long)NTC, 0, (long long)DM * DFF, 0, (long long)NFF, DFF, 1);
        mma_nth16<<<dim3(DM / 128, rows / 64, 2), 128>>>(
            FFN, w2T, b2v, TMP, DFF, DFF, DFF, DM,
            2, 0, (long long)NFF, 0, (long long)DFF * DM, 0, (long long)NTC, DM, 0);

        ln_add<<<rows, 256>>>(Xv, TMP,       lg + 4 * DM, lb + 4 * DM, Xv);
        ln_add<<<rows, 256>>>(Xq, TMP + NTC, lg + 5 * DM, lb + 5 * DM, Xq);
    }

    // --- final bilinear attention pooling ---
    float* PQs = QKV;
    float* Ts  = QKV + NTC;
    vmul_k<<<(NTC + 255) / 256, 256>>>(Xv, att_w, PQs, NTC);
    mma_nt2h<<<dim3(NS / 128, NS / 64, BB), 128>>>(
        PQs, Xq, SC, DM, DM, DM, NS,
        1, SBATCH, 0, SBATCH, 0, (long long)NS * NS, 0, 1.0f);
    softmax_final<<<BB * NS, 256>>>(SC, v_mask, q_mask, att_b);
    mma_nn2h<<<dim3(DM / 128, NS / 64, BB), 128>>>(
        SC, Xq, (const float*)nullptr, Ts, NS, NS, DM, DM,
        1, (long long)NS * NS, 0, SBATCH, 0, SBATCH, 0, 0, 0);
    final_out_k<<<BB, 512>>>(Xv, Ts, (float*)d_out);
}

// round 17
// speedup vs baseline: 1.1413x; 1.0159x over previous
#include <cuda_runtime.h>
#include <cuda_bf16.h>
#include <cuda_fp16.h>
#include <cstdint>

// ---------------------------------------------------------------------------
// CoAttention R16: R15 + cross-QKV z=3 batching + paired LayerNorm launches.
// ---------------------------------------------------------------------------

#define BB    8
#define NS    512
#define DM    512
#define NHEAD 8
#define DHH   64
#define DFF   2048
#define NLAY  4
#define LN_EPS 1e-5f

#define NTC (BB*NS*DM)
#define NFF (BB*NS*DFF)

// ------------------------------- scratch -----------------------------------
__device__ float g_x  [2*NTC];      // V,Q states
__device__ float g_xa [4*NTC];      // VA, QA, VQ, QV
__device__ float g_qkv[6*NTC];
__device__ float g_ao [2*NTC];
__device__ float g_tmp[2*NTC];
__device__ float g_ffn[2*NFF];
__device__ float g_sc [BB*NS*NS];

__device__ __half h_attn_w [NLAY*4*3*DM*DM];
__device__ __half h_attn_wo[NLAY*4*DM*DM];
__device__ __half h_ffn_w1 [NLAY*2*(long long)DM*DFF];
__device__ __half h_ffn_w2 [NLAY*2*(long long)DFF*DM];

// ------------------------------- helpers -----------------------------------

__device__ __forceinline__ unsigned f2h2(float a, float b) {
    __half2 h = __floats2half2_rn(a, b);
    return *reinterpret_cast<unsigned*>(&h);
}

__device__ __forceinline__ void mma16816(float* c, const unsigned* a, const unsigned* b) {
    asm volatile(
        "mma.sync.aligned.m16n8k16.row.col.f32.f16.f16.f32 "
        "{%0,%1,%2,%3}, {%4,%5,%6,%7}, {%8,%9}, {%0,%1,%2,%3};\n"
        : "+f"(c[0]), "+f"(c[1]), "+f"(c[2]), "+f"(c[3])
        : "r"(a[0]), "r"(a[1]), "r"(a[2]), "r"(a[3]), "r"(b[0]), "r"(b[1]));
}

#define LDSM4(r0, r1, r2, r3, addr) \
    asm volatile("ldmatrix.sync.aligned.m8n8.x4.shared.b16 {%0,%1,%2,%3}, [%4];" \
        : "=r"(r0), "=r"(r1), "=r"(r2), "=r"(r3) : "r"(addr))

#define SH 40
#define ROWB 80
#define A2BUF (64  * ROWB)
#define B2BUF (128 * ROWB)

#define FA_KSTRB 144
#define FA_VSTRB 272

// ------------------------------- kernels -----------------------------------

__global__ void copy_k(const float* __restrict__ src, float* __restrict__ dst, int n) {
    int i = blockIdx.x * blockDim.x + threadIdx.x;
    if (i < n) dst[i] = src[i];
}

__global__ __launch_bounds__(256) void transpose_w(
    const float* __restrict__ X, __half* __restrict__ Y, int R, int C)
{
    long long mat = blockIdx.z;
    X += mat * (long long)R * C;
    Y += mat * (long long)R * C;
    __shared__ float t[32][33];
    int c0 = blockIdx.x * 32, r0 = blockIdx.y * 32;
    int tx = threadIdx.x, ty = threadIdx.y;
    #pragma unroll
    for (int j = 0; j < 32; j += 8)
        t[ty + j][tx] = X[(long long)(r0 + ty + j) * C + c0 + tx];
    __syncthreads();
    #pragma unroll
    for (int j = 0; j < 32; j += 8)
        Y[(long long)(c0 + ty + j) * R + r0 + tx] = __float2half_rn(t[tx][ty + j]);
}

// ======== weight GEMM: A fp32 [M,K], B fp16 pre-transposed [N,K] ===========
__global__ __launch_bounds__(128) void mma_nth16(
    const float* __restrict__ A, const __half* __restrict__ Bh,
    const float* __restrict__ bias, float* __restrict__ C,
    int K, int lda, int ldb, int ldc,
    int zdiv, long long sA1, long long sA2, long long sB1, long long sB2,
    long long sC1, long long sC2, long long sBias, int relu)
{
    int z = blockIdx.z;
    int z1 = z / zdiv, z2 = z - z1 * zdiv;
    A  += z1 * sA1 + (long long)z2 * sA2;
    Bh += z1 * sB1 + (long long)z2 * sB2;
    C  += z1 * sC1 + (long long)z2 * sC2;
    if (bias) bias += (long long)z * sBias;

    __shared__ __align__(16) __half As[2][64][SH];
    __shared__ __align__(16) __half Bs[2][128][SH];

    const int tid = threadIdx.x;
    const int wid = tid >> 5, lane = tid & 31;
    const int wm = (wid >> 1) * 32, wn = (wid & 1) * 64;
    const int g = lane >> 2, t4 = lane & 3;
    const int row0 = blockIdx.y * 64, col0 = blockIdx.x * 128;

    const int a_r = tid >> 1, a_kh = (tid & 1) * 16;
    const float* Aptr = A + (long long)(row0 + a_r) * lda + a_kh;

    const int lr = lane & 7, sel = lane >> 3;
    unsigned as0 = (unsigned)__cvta_generic_to_shared(&As[0][0][0]);
    unsigned bs0 = (unsigned)__cvta_generic_to_shared(&Bs[0][0][0]);
    unsigned aaddr = as0 + (unsigned)((wm + (sel & 1) * 8 + lr) * ROWB + (sel >> 1) * 16);
    unsigned baddr[4];
    #pragma unroll
    for (int j = 0; j < 4; j++)
        baddr[j] = bs0 + (unsigned)((wn + j * 16 + (sel >> 1) * 8 + lr) * ROWB + (sel & 1) * 16);

    float acc[2][8][4];
    #pragma unroll
    for (int mi = 0; mi < 2; mi++)
        #pragma unroll
        for (int ni = 0; ni < 8; ni++)
            #pragma unroll
            for (int r = 0; r < 4; r++) acc[mi][ni][r] = 0.f;

    {
        unsigned ah[8];
        uint4 bv[4];
        #pragma unroll
        for (int i = 0; i < 4; i++) {
            float4 v = *(const float4*)(Aptr + i * 4);
            ah[2 * i]     = f2h2(v.x, v.y);
            ah[2 * i + 1] = f2h2(v.z, v.w);
        }
        #pragma unroll
        for (int i = 0; i < 4; i++) {
            int lin = i * 128 + tid;
            int br = lin >> 2, bq = (lin & 3) * 8;
            bv[i] = *(const uint4*)(Bh + (long long)(col0 + br) * ldb + bq);
        }
        *(uint4*)(&As[0][a_r][a_kh])     = make_uint4(ah[0], ah[1], ah[2], ah[3]);
        *(uint4*)(&As[0][a_r][a_kh + 8]) = make_uint4(ah[4], ah[5], ah[6], ah[7]);
        #pragma unroll
        for (int i = 0; i < 4; i++) {
            int lin = i * 128 + tid;
            int br = lin >> 2, bq = (lin & 3) * 8;
            *(uint4*)(&Bs[0][br][bq]) = bv[i];
        }
    }
    __syncthreads();

    const int nk = K >> 5;
    for (int t = 0; t < nk; t++) {
        const int buf = t & 1;
        unsigned ah[8];
        uint4 bv[4];
        if (t + 1 < nk) {
            int k0 = (t + 1) << 5;
            #pragma unroll
            for (int i = 0; i < 4; i++) {
                float4 v = *(const float4*)(Aptr + k0 + i * 4);
                ah[2 * i]     = f2h2(v.x, v.y);
                ah[2 * i + 1] = f2h2(v.z, v.w);
            }
            #pragma unroll
            for (int i = 0; i < 4; i++) {
                int lin = i * 128 + tid;
                int br = lin >> 2, bq = (lin & 3) * 8;
                bv[i] = *(const uint4*)(Bh + (long long)(col0 + br) * ldb + k0 + bq);
            }
        }

        #pragma unroll
        for (int ks = 0; ks < 2; ks++) {
            unsigned ko = (unsigned)(ks * 32);
            unsigned ao = (unsigned)(buf * A2BUF) + ko;
            unsigned bo = (unsigned)(buf * B2BUF) + ko;
            unsigned af0[4], af1[4], bf[4][4];
            LDSM4(af0[0], af0[1], af0[2], af0[3], aaddr + ao);
            LDSM4(af1[0], af1[1], af1[2], af1[3], aaddr + 16u * ROWB + ao);
            #pragma unroll
            for (int j = 0; j < 4; j++)
                LDSM4(bf[j][0], bf[j][1], bf[j][2], bf[j][3], baddr[j] + bo);
            #pragma unroll
            for (int j = 0; j < 4; j++) {
                mma16816(acc[0][2 * j],     af0, &bf[j][0]);
                mma16816(acc[0][2 * j + 1], af0, &bf[j][2]);
                mma16816(acc[1][2 * j],     af1, &bf[j][0]);
                mma16816(acc[1][2 * j + 1], af1, &bf[j][2]);
            }
        }

        if (t + 1 < nk) {
            const int nb = (t + 1) & 1;
            *(uint4*)(&As[nb][a_r][a_kh])     = make_uint4(ah[0], ah[1], ah[2], ah[3]);
            *(uint4*)(&As[nb][a_r][a_kh + 8]) = make_uint4(ah[4], ah[5], ah[6], ah[7]);
            #pragma unroll
            for (int i = 0; i < 4; i++) {
                int lin = i * 128 + tid;
                int br = lin >> 2, bq = (lin & 3) * 8;
                *(uint4*)(&Bs[nb][br][bq]) = bv[i];
            }
            __syncthreads();
        }
    }

    #pragma unroll
    for (int mi = 0; mi < 2; mi++)
        #pragma unroll
        for (int ni = 0; ni < 8; ni++) {
            int r = row0 + wm + mi * 16 + g;
            int c = col0 + wn + ni * 8 + 2 * t4;
            float b0v = 0.f, b1v = 0.f;
            if (bias) { b0v = bias[c]; b1v = bias[c + 1]; }
            float o0 = acc[mi][ni][0] + b0v;
            float o1 = acc[mi][ni][1] + b1v;
            float o2 = acc[mi][ni][2] + b0v;
            float o3 = acc[mi][ni][3] + b1v;
            if (relu) {
                o0 = fmaxf(o0, 0.f); o1 = fmaxf(o1, 0.f);
                o2 = fmaxf(o2, 0.f); o3 = fmaxf(o3, 0.f);
            }
            *(float2*)(C + (long long)r * ldc + c)       = make_float2(o0, o1);
            *(float2*)(C + (long long)(r + 8) * ldc + c) = make_float2(o2, o3);
        }
}

// ======== NN GEMM fp32-B (final bilinear: SC @ Q) ==========================
__global__ __launch_bounds__(128) void mma_nn2h(
    const float* __restrict__ A, const float* __restrict__ B,
    const float* __restrict__ bias, float* __restrict__ C,
    int K, int lda, int ldb, int ldc,
    int zdiv, long long sA1, long long sA2, long long sB1, long long sB2,
    long long sC1, long long sC2, long long sBias, int relu)
{
    int z = blockIdx.z;
    int z1 = z / zdiv, z2 = z - z1 * zdiv;
    A += z1 * sA1 + (long long)z2 * sA2;
    B += z1 * sB1 + (long long)z2 * sB2;
    C += z1 * sC1 + (long long)z2 * sC2;
    if (bias) bias += (long long)z * sBias;

    __shared__ __align__(16) __half As[2][64][SH];
    __shared__ __align__(16) __half Bs[2][128][SH];

    const int tid = threadIdx.x;
    const int wid = tid >> 5, lane = tid & 31;
    const int wm = (wid >> 1) * 32, wn = (wid & 1) * 64;
    const int g = lane >> 2, t4 = lane & 3;
    const int row0 = blockIdx.y * 64, col0 = blockIdx.x * 128;

    const int a_r = tid >> 1, a_kh = (tid & 1) * 16;
    const float* Aptr = A + (long long)(row0 + a_r) * lda + a_kh;
    const float* Bptr = B + col0 + tid;

    const int lr = lane & 7, sel = lane >> 3;
    unsigned as0 = (unsigned)__cvta_generic_to_shared(&As[0][0][0]);
    unsigned bs0 = (unsigned)__cvta_generic_to_shared(&Bs[0][0][0]);
    unsigned aaddr = as0 + (unsigned)((wm + (sel & 1) * 8 + lr) * ROWB + (sel >> 1) * 16);
    unsigned baddr[4];
    #pragma unroll
    for (int j = 0; j < 4; j++)
        baddr[j] = bs0 + (unsigned)((wn + j * 16 + (sel >> 1) * 8 + lr) * ROWB + (sel & 1) * 16);

    float acc[2][8][4];
    #pragma unroll
    for (int mi = 0; mi < 2; mi++)
        #pragma unroll
        for (int ni = 0; ni < 8; ni++)
            #pragma unroll
            for (int r = 0; r < 4; r++) acc[mi][ni][r] = 0.f;

    {
        unsigned ah[8], bh[16];
        #pragma unroll
        for (int i = 0; i < 4; i++) {
            float4 v = *(const float4*)(Aptr + i * 4);
            ah[2 * i]     = f2h2(v.x, v.y);
            ah[2 * i + 1] = f2h2(v.z, v.w);
        }
        #pragma unroll
        for (int j = 0; j < 16; j++)
            bh[j] = f2h2(Bptr[(long long)(2 * j) * ldb], Bptr[(long long)(2 * j + 1) * ldb]);
        *(uint4*)(&As[0][a_r][a_kh])     = make_uint4(ah[0], ah[1], ah[2], ah[3]);
        *(uint4*)(&As[0][a_r][a_kh + 8]) = make_uint4(ah[4], ah[5], ah[6], ah[7]);
        *(uint4*)(&Bs[0][tid][0])  = make_uint4(bh[0],  bh[1],  bh[2],  bh[3]);
        *(uint4*)(&Bs[0][tid][8])  = make_uint4(bh[4],  bh[5],  bh[6],  bh[7]);
        *(uint4*)(&Bs[0][tid][16]) = make_uint4(bh[8],  bh[9],  bh[10], bh[11]);
        *(uint4*)(&Bs[0][tid][24]) = make_uint4(bh[12], bh[13], bh[14], bh[15]);
    }
    __syncthreads();

    const int nk = K >> 5;
    for (int t = 0; t < nk; t++) {
        const int buf = t & 1;
        unsigned ah[8], bh[16];
        if (t + 1 < nk) {
            int k0 = (t + 1) << 5;
            #pragma unroll
            for (int i = 0; i < 4; i++) {
                float4 v = *(const float4*)(Aptr + k0 + i * 4);
                ah[2 * i]     = f2h2(v.x, v.y);
                ah[2 * i + 1] = f2h2(v.z, v.w);
            }
            #pragma unroll
            for (int j = 0; j < 16; j++)
                bh[j] = f2h2(Bptr[(long long)(k0 + 2 * j) * ldb],
                             Bptr[(long long)(k0 + 2 * j + 1) * ldb]);
        }

        #pragma unroll
        for (int ks = 0; ks < 2; ks++) {
            unsigned ko = (unsigned)(ks * 32);
            unsigned ao = (unsigned)(buf * A2BUF) + ko;
            unsigned bo = (unsigned)(buf * B2BUF) + ko;
            unsigned af0[4], af1[4], bf[4][4];
            LDSM4(af0[0], af0[1], af0[2], af0[3], aaddr + ao);
            LDSM4(af1[0], af1[1], af1[2], af1[3], aaddr + 16u * ROWB + ao);
            #pragma unroll
            for (int j = 0; j < 4; j++)
                LDSM4(bf[j][0], bf[j][1], bf[j][2], bf[j][3], baddr[j] + bo);
            #pragma unroll
            for (int j = 0; j < 4; j++) {
                mma16816(acc[0][2 * j],     af0, &bf[j][0]);
                mma16816(acc[0][2 * j + 1], af0, &bf[j][2]);
                mma16816(acc[1][2 * j],     af1, &bf[j][0]);
                mma16816(acc[1][2 * j + 1], af1, &bf[j][2]);
            }
        }

        if (t + 1 < nk) {
            const int nb = (t + 1) & 1;
            *(uint4*)(&As[nb][a_r][a_kh])     = make_uint4(ah[0], ah[1], ah[2], ah[3]);
            *(uint4*)(&As[nb][a_r][a_kh + 8]) = make_uint4(ah[4], ah[5], ah[6], ah[7]);
            *(uint4*)(&Bs[nb][tid][0])  = make_uint4(bh[0],  bh[1],  bh[2],  bh[3]);
            *(uint4*)(&Bs[nb][tid][8])  = make_uint4(bh[4],  bh[5],  bh[6],  bh[7]);
            *(uint4*)(&Bs[nb][tid][16]) = make_uint4(bh[8],  bh[9],  bh[10], bh[11]);
            *(uint4*)(&Bs[nb][tid][24]) = make_uint4(bh[12], bh[13], bh[14], bh[15]);
            __syncthreads();
        }
    }

    #pragma unroll
    for (int mi = 0; mi < 2; mi++)
        #pragma unroll
        for (int ni = 0; ni < 8; ni++) {
            int r = row0 + wm + mi * 16 + g;
            int c = col0 + wn + ni * 8 + 2 * t4;
            float b0v = 0.f, b1v = 0.f;
            if (bias) { b0v = bias[c]; b1v = bias[c + 1]; }
            float o0 = acc[mi][ni][0] + b0v;
            float o1 = acc[mi][ni][1] + b1v;
            float o2 = acc[mi][ni][2] + b0v;
            float o3 = acc[mi][ni][3] + b1v;
            if (relu) {
                o0 = fmaxf(o0, 0.f); o1 = fmaxf(o1, 0.f);
                o2 = fmaxf(o2, 0.f); o3 = fmaxf(o3, 0.f);
            }
            *(float2*)(C + (long long)r * ldc + c)       = make_float2(o0, o1);
            *(float2*)(C + (long long)(r + 8) * ldc + c) = make_float2(o2, o3);
        }
}

// ======== NT GEMM fp32-B (final bilinear: PQs @ Q^T) =======================
__global__ __launch_bounds__(128) void mma_nt2h(
    const float* __restrict__ A, const float* __restrict__ B,
    float* __restrict__ C,
    int K, int lda, int ldb, int ldc,
    int zdiv, long long sA1, long long sA2, long long sB1, long long sB2,
    long long sC1, long long sC2, float scale)
{
    int z = blockIdx.z;
    int z1 = z / zdiv, z2 = z - z1 * zdiv;
    A += z1 * sA1 + (long long)z2 * sA2;
    B += z1 * sB1 + (long long)z2 * sB2;
    C += z1 * sC1 + (long long)z2 * sC2;

    __shared__ __align__(16) __half As[2][64][SH];
    __shared__ __align__(16) __half Bs[2][128][SH];

    const int tid = threadIdx.x;
    const int wid = tid >> 5, lane = tid & 31;
    const int wm = (wid >> 1) * 32, wn = (wid & 1) * 64;
    const int g = lane >> 2, t4 = lane & 3;
    const int row0 = blockIdx.y * 64, col0 = blockIdx.x * 128;

    const int a_r = tid >> 1, a_kh = (tid & 1) * 16;
    const float* Aptr = A + (long long)(row0 + a_r) * lda + a_kh;
    const float* Bptr = B + (long long)(col0 + tid) * ldb;

    const int lr = lane & 7, sel = lane >> 3;
    unsigned as0 = (unsigned)__cvta_generic_to_shared(&As[0][0][0]);
    unsigned bs0 = (unsigned)__cvta_generic_to_shared(&Bs[0][0][0]);
    unsigned aaddr = as0 + (unsigned)((wm + (sel & 1) * 8 + lr) * ROWB + (sel >> 1) * 16);
    unsigned baddr[4];
    #pragma unroll
    for (int j = 0; j < 4; j++)
        baddr[j] = bs0 + (unsigned)((wn + j * 16 + (sel >> 1) * 8 + lr) * ROWB + (sel & 1) * 16);

    float acc[2][8][4];
    #pragma unroll
    for (int mi = 0; mi < 2; mi++)
        #pragma unroll
        for (int ni = 0; ni < 8; ni++)
            #pragma unroll
            for (int r = 0; r < 4; r++) acc[mi][ni][r] = 0.f;

    {
        unsigned ah[8], bh[16];
        #pragma unroll
        for (int i = 0; i < 4; i++) {
            float4 v = *(const float4*)(Aptr + i * 4);
            ah[2 * i]     = f2h2(v.x, v.y);
            ah[2 * i + 1] = f2h2(v.z, v.w);
        }
        #pragma unroll
        for (int i = 0; i < 8; i++) {
            float4 v = *(const float4*)(Bptr + i * 4);
            bh[2 * i]     = f2h2(v.x, v.y);
            bh[2 * i + 1] = f2h2(v.z, v.w);
        }
        *(uint4*)(&As[0][a_r][a_kh])     = make_uint4(ah[0], ah[1], ah[2], ah[3]);
        *(uint4*)(&As[0][a_r][a_kh + 8]) = make_uint4(ah[4], ah[5], ah[6], ah[7]);
        *(uint4*)(&Bs[0][tid][0])  = make_uint4(bh[0],  bh[1],  bh[2],  bh[3]);
        *(uint4*)(&Bs[0][tid][8])  = make_uint4(bh[4],  bh[5],  bh[6],  bh[7]);
        *(uint4*)(&Bs[0][tid][16]) = make_uint4(bh[8],  bh[9],  bh[10], bh[11]);
        *(uint4*)(&Bs[0][tid][24]) = make_uint4(bh[12], bh[13], bh[14], bh[15]);
    }
    __syncthreads();

    const int nk = K >> 5;
    for (int t = 0; t < nk; t++) {
        const int buf = t & 1;
        unsigned ah[8], bh[16];
        if (t + 1 < nk) {
            int k0 = (t + 1) << 5;
            #pragma unroll
            for (int i = 0; i < 4; i++) {
                float4 v = *(const float4*)(Aptr + k0 + i * 4);
                ah[2 * i]     = f2h2(v.x, v.y);
                ah[2 * i + 1] = f2h2(v.z, v.w);
            }
            #pragma unroll
            for (int i = 0; i < 8; i++) {
                float4 v = *(const float4*)(Bptr + k0 + i * 4);
                bh[2 * i]     = f2h2(v.x, v.y);
                bh[2 * i + 1] = f2h2(v.z, v.w);
            }
        }

        #pragma unroll
        for (int ks = 0; ks < 2; ks++) {
            unsigned ko = (unsigned)(ks * 32);
            unsigned ao = (unsigned)(buf * A2BUF) + ko;
            unsigned bo = (unsigned)(buf * B2BUF) + ko;
            unsigned af0[4], af1[4], bf[4][4];
            LDSM4(af0[0], af0[1], af0[2], af0[3], aaddr + ao);
            LDSM4(af1[0], af1[1], af1[2], af1[3], aaddr + 16u * ROWB + ao);
            #pragma unroll
            for (int j = 0; j < 4; j++)
                LDSM4(bf[j][0], bf[j][1], bf[j][2], bf[j][3], baddr[j] + bo);
            #pragma unroll
            for (int j = 0; j < 4; j++) {
                mma16816(acc[0][2 * j],     af0, &bf[j][0]);
                mma16816(acc[0][2 * j + 1], af0, &bf[j][2]);
                mma16816(acc[1][2 * j],     af1, &bf[j][0]);
                mma16816(acc[1][2 * j + 1], af1, &bf[j][2]);
            }
        }

        if (t + 1 < nk) {
            const int nb = (t + 1) & 1;
            *(uint4*)(&As[nb][a_r][a_kh])     = make_uint4(ah[0], ah[1], ah[2], ah[3]);
            *(uint4*)(&As[nb][a_r][a_kh + 8]) = make_uint4(ah[4], ah[5], ah[6], ah[7]);
            *(uint4*)(&Bs[nb][tid][0])  = make_uint4(bh[0],  bh[1],  bh[2],  bh[3]);
            *(uint4*)(&Bs[nb][tid][8])  = make_uint4(bh[4],  bh[5],  bh[6],  bh[7]);
            *(uint4*)(&Bs[nb][tid][16]) = make_uint4(bh[8],  bh[9],  bh[10], bh[11]);
            *(uint4*)(&Bs[nb][tid][24]) = make_uint4(bh[12], bh[13], bh[14], bh[15]);
            __syncthreads();
        }
    }

    #pragma unroll
    for (int mi = 0; mi < 2; mi++)
        #pragma unroll
        for (int ni = 0; ni < 8; ni++) {
            int r = row0 + wm + mi * 16 + g;
            int c = col0 + wn + ni * 8 + 2 * t4;
            *(float2*)(C + (long long)r * ldc + c) =
                make_float2(acc[mi][ni][0] * scale, acc[mi][ni][1] * scale);
            *(float2*)(C + (long long)(r + 8) * ldc + c) =
                make_float2(acc[mi][ni][2] * scale, acc[mi][ni][3] * scale);
        }
}

// ======== fused flash attention (1 or 2 batched attentions) ================
__global__ __launch_bounds__(128, 4) void flash_attn(
    const float* __restrict__ QKV, const int* __restrict__ mask0,
    const int* __restrict__ mask1, float* __restrict__ Og)
{
    __shared__ __align__(16) __half Qs[64 * (FA_KSTRB / 2)];
    __shared__ __align__(16) __half Ks[128 * (FA_KSTRB / 2)];
    __shared__ __align__(16) __half Vs[64 * (FA_VSTRB / 2)];
    __shared__ float msk[NS];

    const int a  = blockIdx.y >> 6;
    const int bh = blockIdx.y & 63;
    const int b = bh >> 3, h = bh & 7;
    const int q0 = blockIdx.x * 64;
    const int* mask = a ? mask1 : mask0;
    const float* Qg = QKV + (long long)a * 3 * NTC;
    const float* Qp = Qg + (long long)b * NS * DM + h * DHH;
    const float* Kp = Qp + NTC;
    const float* Vp = Qp + 2 * NTC;
    float* Ob = Og + (long long)a * NTC;

    const int tid = threadIdx.x;
    const int wid = tid >> 5, lane = tid & 31;
    const int g = lane >> 2, t4 = lane & 3;
    const int lr = lane & 7, sel = lane >> 3;

    unsigned qs_b = (unsigned)__cvta_generic_to_shared(Qs);
    unsigned ks_b = (unsigned)__cvta_generic_to_shared(Ks);
    unsigned vs_b = (unsigned)__cvta_generic_to_shared(Vs);

    for (int j = tid; j < NS; j += 128)
        msk[j] = mask[b * NS + j] ? 0.f : -1e9f;

    {
        int r = tid >> 1, kh = (tid & 1) * 32;
        const float* qp = Qp + (long long)(q0 + r) * DM + kh;
        __half* dst = Qs + r * (FA_KSTRB / 2) + kh;
        #pragma unroll
        for (int i = 0; i < 8; i++) {
            float4 v = *(const float4*)(qp + i * 4);
            *(uint2*)(dst + i * 4) = make_uint2(f2h2(v.x, v.y), f2h2(v.z, v.w));
        }
    }

    unsigned qa = qs_b + (unsigned)((wid * 16 + (sel & 1) * 8 + lr) * FA_KSTRB + (sel >> 1) * 16);

    float m0 = -1e30f, m1 = -1e30f, l0 = 0.f, l1 = 0.f;
    float o[8][4];
    #pragma unroll
    for (int p = 0; p < 8; p++)
        #pragma unroll
        for (int r = 0; r < 4; r++) o[p][r] = 0.f;

    for (int c = 0; c < 4; c++) {
        const int j0 = c * 128;
        {
            const float* kp = Kp + (long long)(j0 + tid) * DM;
            __half* dst = Ks + tid * (FA_KSTRB / 2);
            #pragma unroll
            for (int i = 0; i < 16; i++) {
                float4 v = *(const float4*)(kp + i * 4);
                *(uint2*)(dst + i * 4) = make_uint2(f2h2(v.x, v.y), f2h2(v.z, v.w));
            }
            const float* vp = Vp + (long long)(j0 + tid) * DM;
            __half* base = Vs + tid;
            #pragma unroll
            for (int i = 0; i < 16; i++) {
                float4 v = *(const float4*)(vp + i * 4);
                base[(4 * i + 0) * (FA_VSTRB / 2)] = __float2half_rn(v.x);
                base[(4 * i + 1) * (FA_VSTRB / 2)] = __float2half_rn(v.y);
                base[(4 * i + 2) * (FA_VSTRB / 2)] = __float2half_rn(v.z);
                base[(4 * i + 3) * (FA_VSTRB / 2)] = __float2half_rn(v.w);
            }
        }
        __syncthreads();

        float s[16][4];
        #pragma unroll
        for (int p = 0; p < 16; p++)
            #pragma unroll
            for (int r = 0; r < 4; r++) s[p][r] = 0.f;

        #pragma unroll
        for (int ks = 0; ks < 4; ks++) {
            unsigned af[4];
            LDSM4(af[0], af[1], af[2], af[3], qa + ks * 32);
            #pragma unroll
            for (int p = 0; p < 8; p++) {
                unsigned bf[4];
                unsigned ba = ks_b + (unsigned)((p * 16 + (sel >> 1) * 8 + lr) * FA_KSTRB
                                                + (sel & 1) * 16) + ks * 32;
                LDSM4(bf[0], bf[1], bf[2], bf[3], ba);
                mma16816(s[2 * p],     af, &bf[0]);
                mma16816(s[2 * p + 1], af, &bf[2]);
            }
        }

        float cm0 = -1e30f, cm1 = -1e30f;
        #pragma unroll
        for (int p = 0; p < 16; p++) {
            int col = j0 + p * 8 + 2 * t4;
            float mv0 = msk[col], mv1 = msk[col + 1];
            s[p][0] = s[p][0] * 0.125f + mv0;
            s[p][1] = s[p][1] * 0.125f + mv1;
            s[p][2] = s[p][2] * 0.125f + mv0;
            s[p][3] = s[p][3] * 0.125f + mv1;
            cm0 = fmaxf(cm0, fmaxf(s[p][0], s[p][1]));
            cm1 = fmaxf(cm1, fmaxf(s[p][2], s[p][3]));
        }
        cm0 = fmaxf(cm0, __shfl_xor_sync(0xffffffffu, cm0, 1));
        cm0 = fmaxf(cm0, __shfl_xor_sync(0xffffffffu, cm0, 2));
        cm1 = fmaxf(cm1, __shfl_xor_sync(0xffffffffu, cm1, 1));
        cm1 = fmaxf(cm1, __shfl_xor_sync(0xffffffffu, cm1, 2));

        float nm0 = fmaxf(m0, cm0), nm1 = fmaxf(m1, cm1);
        float sc0 = __expf(m0 - nm0), sc1 = __expf(m1 - nm1);
        m0 = nm0; m1 = nm1;
        l0 *= sc0; l1 *= sc1;
        #pragma unroll
        for (int p = 0; p < 8; p++) {
            o[p][0] *= sc0; o[p][1] *= sc0;
            o[p][2] *= sc1; o[p][3] *= sc1;
        }

        #pragma unroll
        for (int p = 0; p < 16; p++) {
            s[p][0] = __expf(s[p][0] - m0);
            s[p][1] = __expf(s[p][1] - m0);
            s[p][2] = __expf(s[p][2] - m1);
            s[p][3] = __expf(s[p][3] - m1);
            l0 += s[p][0] + s[p][1];
            l1 += s[p][2] + s[p][3];
        }

        #pragma unroll
        for (int p = 0; p < 8; p++) {
            unsigned af[4];
            af[0] = f2h2(s[2 * p][0],     s[2 * p][1]);
            af[1] = f2h2(s[2 * p][2],     s[2 * p][3]);
            af[2] = f2h2(s[2 * p + 1][0], s[2 * p + 1][1]);
            af[3] = f2h2(s[2 * p + 1][2], s[2 * p + 1][3]);
            #pragma unroll
            for (int n = 0; n < 4; n++) {
                unsigned bf[4];
                unsigned ba = vs_b + (unsigned)((n * 16 + (sel >> 1) * 8 + lr) * FA_VSTRB
                                                + ((sel & 1) * 8 + p * 16) * 2);
                LDSM4(bf[0], bf[1], bf[2], bf[3], ba);
                mma16816(o[2 * n],     af, &bf[0]);
                mma16816(o[2 * n + 1], af, &bf[2]);
            }
        }
        __syncthreads();
    }

    l0 += __shfl_xor_sync(0xffffffffu, l0, 1);
    l0 += __shfl_xor_sync(0xffffffffu, l0, 2);
    l1 += __shfl_xor_sync(0xffffffffu, l1, 1);
    l1 += __shfl_xor_sync(0xffffffffu, l1, 2);
    const float inv0 = 1.f / l0, inv1 = 1.f / l1;

    {
        int r0 = q0 + wid * 16 + g;
        float* out0 = Ob + ((long long)b * NS + r0) * DM + h * DHH;
        float* out1 = out0 + 8ll * DM;
        #pragma unroll
        for (int p = 0; p < 8; p++) {
            int cc = p * 8 + 2 * t4;
            *(float2*)(out0 + cc) = make_float2(o[p][0] * inv0, o[p][1] * inv0);
            *(float2*)(out1 + cc) = make_float2(o[p][2] * inv1, o[p][3] * inv1);
        }
    }
}

// paired residual+LN: grid (rows, 2); half a uses offsets a*sX / a*DM.
__global__ __launch_bounds__(256) void ln_add2(
    const float* __restrict__ X, const float* __restrict__ Y,
    const float* __restrict__ g, const float* __restrict__ be,
    float* __restrict__ O,
    long long sX, long long sY, long long sO)
{
    int row = blockIdx.x;
    int a = blockIdx.y;
    const float* xp = X + a * sX + (long long)row * DM;
    const float* yp = Y + a * sY + (long long)row * DM;
    float* op = O + a * sO + (long long)row * DM;
    g  += a * DM;
    be += a * DM;
    int tid = threadIdx.x;

    float a0 = xp[tid] + yp[tid];
    float a1 = xp[tid + 256] + yp[tid + 256];

    __shared__ float r1[256];
    __shared__ float r2[256];
    r1[tid] = a0 + a1;
    r2[tid] = a0 * a0 + a1 * a1;
    __syncthreads();
    for (int s = 128; s > 0; s >>= 1) {
        if (tid < s) { r1[tid] += r1[tid + s]; r2[tid] += r2[tid + s]; }
        __syncthreads();
    }
    float mean = r1[0] * (1.f / DM);
    float var  = r2[0] * (1.f / DM) - mean * mean;
    float rstd = rsqrtf(var + LN_EPS);
    op[tid]       = (a0 - mean) * rstd * g[tid]       + be[tid];
    op[tid + 256] = (a1 - mean) * rstd * g[tid + 256] + be[tid + 256];
}

__global__ void vmul_k(const float* __restrict__ v, const float* __restrict__ w,
                       float* __restrict__ o, int n) {
    int i = blockIdx.x * blockDim.x + threadIdx.x;
    if (i < n) o[i] = v[i] * w[i & (DM - 1)];
}

__global__ __launch_bounds__(256) void softmax_final(
    float* __restrict__ S, const int* __restrict__ vmask,
    const int* __restrict__ qmask, const float* __restrict__ attb)
{
    int row = blockIdx.x;
    int b = row >> 9, i = row & (NS - 1);
    int rowpad = (vmask[b * NS + i] == 0);
    float ab = attb[0];
    float* Sp = S + (long long)row * NS;
    int tid = threadIdx.x;

    float v0 = (rowpad || qmask[b * NS + tid] == 0)       ? -1e9f : Sp[tid] + ab;
    float v1 = (rowpad || qmask[b * NS + tid + 256] == 0) ? -1e9f : Sp[tid + 256] + ab;

    __shared__ float red[256];
    red[tid] = fmaxf(v0, v1);
    __syncthreads();
    for (int s = 128; s > 0; s >>= 1) {
        if (tid < s) red[tid] = fmaxf(red[tid], red[tid + s]);
        __syncthreads();
    }
    float m = red[0];
    __syncthreads();

    float e0 = __expf(v0 - m), e1 = __expf(v1 - m);
    red[tid] = e0 + e1;
    __syncthreads();
    for (int s = 128; s > 0; s >>= 1) {
        if (tid < s) red[tid] += red[tid + s];
        __syncthreads();
    }
    float inv = 1.f / red[0];
    Sp[tid]       = e0 * inv;
    Sp[tid + 256] = e1 * inv;
}

__global__ void final_out_k(const float* __restrict__ V, const float* __restrict__ T,
                            float* __restrict__ out) {
    int b = blockIdx.x;
    int k = threadIdx.x;
    const float* vp = V + (long long)b * NS * DM;
    const float* tp = T + (long long)b * NS * DM;
    float acc = 0.f;
    #pragma unroll 4
    for (int i = 0; i < NS; i++)
        acc = fmaf(vp[(long long)i * DM + k], tp[(long long)i * DM + k], acc);
    out[b * DM + k] = acc * (1.f / 512.f);
}

// ------------------------------- host side ---------------------------------

extern "C" void kernel_launch(void* const* d_in, const int* in_sizes, int n_in,
                              void* d_out, int out_size)
{
    const float *v_in, *q_in, *attn_w, *attn_b, *attn_wo, *attn_bo;
    const float *ln_g, *ln_b, *fw1, *fb1, *fw2, *fb2, *att_w, *att_b;
    const int *v_mask, *q_mask;

    if (in_sizes[2] == BB * NS) {   // dict order
        v_in    = (const float*)d_in[0];
        q_in    = (const float*)d_in[1];
        v_mask  = (const int*)  d_in[2];
        q_mask  = (const int*)  d_in[3];
        attn_w  = (const float*)d_in[4];
        attn_b  = (const float*)d_in[5];
        attn_wo = (const float*)d_in[6];
        attn_bo = (const float*)d_in[7];
        ln_g    = (const float*)d_in[8];
        ln_b    = (const float*)d_in[9];
        fw1     = (const float*)d_in[10];
        fb1     = (const float*)d_in[11];
        fw2     = (const float*)d_in[12];
        fb2     = (const float*)d_in[13];
        att_w   = (const float*)d_in[14];
        att_b   = (const float*)d_in[15];
    } else {                        // signature order
        v_in    = (const float*)d_in[0];
        q_in    = (const float*)d_in[1];
        attn_w  = (const float*)d_in[2];
        attn_b  = (const float*)d_in[3];
        attn_wo = (const float*)d_in[4];
        attn_bo = (const float*)d_in[5];
        ln_g    = (const float*)d_in[6];
        ln_b    = (const float*)d_in[7];
        fw1     = (const float*)d_in[8];
        fb1     = (const float*)d_in[9];
        fw2     = (const float*)d_in[10];
        fb2     = (const float*)d_in[11];
        att_w   = (const float*)d_in[12];
        att_b   = (const float*)d_in[13];
        v_mask  = (const int*)  d_in[14];
        q_mask  = (const int*)  d_in[15];
    }

    float *X, *XA, *QKV, *AO, *TMP, *FFN, *SC;
    __half *HW, *HWO, *HF1, *HF2;
    cudaGetSymbolAddress((void**)&X,   g_x);
    cudaGetSymbolAddress((void**)&XA,  g_xa);
    cudaGetSymbolAddress((void**)&QKV, g_qkv);
    cudaGetSymbolAddress((void**)&AO,  g_ao);
    cudaGetSymbolAddress((void**)&TMP, g_tmp);
    cudaGetSymbolAddress((void**)&FFN, g_ffn);
    cudaGetSymbolAddress((void**)&SC,  g_sc);
    cudaGetSymbolAddress((void**)&HW,  h_attn_w);
    cudaGetSymbolAddress((void**)&HWO, h_attn_wo);
    cudaGetSymbolAddress((void**)&HF1, h_ffn_w1);
    cudaGetSymbolAddress((void**)&HF2, h_ffn_w2);

    float* Xv = X;
    float* Xq = X + NTC;
    float* VA = XA;
    float* QA = XA + NTC;
    float* VQ = XA + 2ll * NTC;
    float* QV = XA + 3ll * NTC;

    const long long WS = (long long)DM * DM;
    const long long SBATCH = (long long)NS * DM;
    const int rows = BB * NS;
    const dim3 gP(DM / 128, rows / 64, 1);

    dim3 tb(32, 8, 1);
    transpose_w<<<dim3(DM / 32, DM / 32, NLAY * 4 * 3), tb>>>(attn_w,  HW,  DM, DM);
    transpose_w<<<dim3(DM / 32, DM / 32, NLAY * 4),     tb>>>(attn_wo, HWO, DM, DM);
    transpose_w<<<dim3(DFF / 32, DM / 32, NLAY * 2),    tb>>>(fw1, HF1, DM, DFF);
    transpose_w<<<dim3(DM / 32, DFF / 32, NLAY * 2),    tb>>>(fw2, HF2, DFF, DM);

    copy_k<<<(NTC + 255) / 256, 256>>>(v_in, Xv, NTC);
    copy_k<<<(NTC + 255) / 256, 256>>>(q_in, Xq, NTC);

    for (int i = 0; i < NLAY; i++) {
        const __half* wT  = HW  + (long long)i * 4 * 3 * WS;
        const __half* woT = HWO + (long long)i * 4 * WS;
        const float* ab  = attn_b  + (long long)i * 4 * 3 * DM;
        const float* abo = attn_bo + (long long)i * 4 * DM;
        const float* lg  = ln_g + (long long)i * 6 * DM;
        const float* lb  = ln_b + (long long)i * 6 * DM;

        // --- paired self-attention ---
        mma_nth16<<<dim3(DM / 128, rows / 64, 6), 128>>>(
            X, wT, ab, QKV, DM, DM, DM, DM,
            3, (long long)NTC, 0, 3 * WS, WS, 3ll * NTC, (long long)NTC, DM, 0);
        flash_attn<<<dim3(NS / 64, 128), 128>>>(QKV, v_mask, q_mask, AO);
        mma_nth16<<<dim3(DM / 128, rows / 64, 2), 128>>>(
            AO, woT, abo, TMP, DM, DM, DM, DM,
            2, 0, (long long)NTC, 0, WS, 0, (long long)NTC, DM, 0);

        ln_add2<<<dim3(rows, 2), 256>>>(X, TMP, lg, lb, XA,
                                        (long long)NTC, (long long)NTC, (long long)NTC);

        // --- cross 1: q = VA, kv = QA -> VQ ---
        mma_nth16<<<dim3(DM / 128, rows / 64, 3), 128>>>(
            VA, wT + 6 * WS, ab + 6 * DM, QKV, DM, DM, DM, DM,
            2, (long long)NTC, (long long)NTC, 2 * WS, WS, 2ll * NTC, (long long)NTC, DM, 0);
        flash_attn<<<dim3(NS / 64, 64), 128>>>(QKV, q_mask, q_mask, AO);
        mma_nth16<<<gP, 128>>>(
            AO, woT + 2 * WS, abo + 2 * DM, VQ, DM, DM, DM, DM,
            1, 0, 0, 0, 0, 0, 0, DM, 0);

        // --- cross 2: q = QA, kv = VQ -> QV ---
        mma_nth16<<<dim3(DM / 128, rows / 64, 3), 128>>>(
            QA, wT + 9 * WS, ab + 9 * DM, QKV, DM, DM, DM, DM,
            2, (long long)NTC, (long long)NTC, 2 * WS, WS, 2ll * NTC, (long long)NTC, DM, 0);
        flash_attn<<<dim3(NS / 64, 64), 128>>>(QKV, v_mask, v_mask, AO);
        mma_nth16<<<gP, 128>>>(
            AO, woT + 3 * WS, abo + 3 * DM, QV, DM, DM, DM, DM,
            1, 0, 0, 0, 0, 0, 0, DM, 0);

        ln_add2<<<dim3(rows, 2), 256>>>(X, VQ, lg + 2 * DM, lb + 2 * DM, X,
                                        (long long)NTC, (long long)NTC, (long long)NTC);

        // --- paired FFN ---
        const __half* w1T = HF1 + (long long)i * 2 * DM * DFF;
        const __half* w2T = HF2 + (long long)i * 2 * DFF * DM;
        const float* b1v = fb1 + (long long)i * 2 * DFF;
        const float* b2v = fb2 + (long long)i * 2 * DM;

        mma_nth16<<<dim3(DFF / 128, rows / 64, 2), 128>>>(
            X, w1T, b1v, FFN, DM, DM, DM, DFF,
            2, 0, (long long)NTC, 0, (long long)DM * DFF, 0, (long long)NFF, DFF, 1);
        mma_nth16<<<dim3(DM / 128, rows / 64, 2), 128>>>(
            FFN, w2T, b2v, TMP, DFF, DFF, DFF, DM,
            2, 0, (long long)NFF, 0, (long long)DFF * DM, 0, (long long)NTC, DM, 0);

        ln_add2<<<dim3(rows, 2), 256>>>(X, TMP, lg + 4 * DM, lb + 4 * DM, X,
                                        (long long)NTC, (long long)NTC, (long long)NTC);
    }

    // --- final bilinear attention pooling ---
    float* PQs = QKV;
    float* Ts  = QKV + NTC;
    vmul_k<<<(NTC + 255) / 256, 256>>>(Xv, att_w, PQs, NTC);
    mma_nt2h<<<dim3(NS / 128, NS / 64, BB), 128>>>(
        PQs, Xq, SC, DM, DM, DM, NS,
        1, SBATCH, 0, SBATCH, 0, (long long)NS * NS, 0, 1.0f);
    softmax_final<<<BB * NS, 256>>>(SC, v_mask, q_mask, att_b);
    mma_nn2h<<<dim3(DM / 128, NS / 64, BB), 128>>>(
        SC, Xq, (const float*)nullptr, Ts, NS, NS, DM, DM,
        1, (long long)NS * NS, 0, SBATCH, 0, SBATCH, 0, 0, 0);
    final_out_k<<<BB, 512>>>(Xv, Ts, (float*)d_out);
}